// round 12
// baseline (speedup 1.0000x reference)
#include <cuda_runtime.h>
#include <math.h>

#define HH 256
#define NN 32
#define CCHN 32
#define LL 2048
#define LF 1025
#define NBATCH 2
#define CSPLIT 8
#define PADN 2176                       // 2048 + 128 pad floats
#define PIX(a) ((a) + ((a) >> 4))

// ---------------- scratch ----------------
__device__ float2 g_tw[2048];                 // e^{-2*pi*i*k/4096}
__device__ float2 g_kf  [CCHN * HH * LF];     // (C,H,1025) 2048-DFT of kernel
__device__ float2 g_k4  [CCHN * HH * 2049];   // unified 4096-DFT half-spectrum (even+odd interleaved)
__device__ float2 g_pdf [NBATCH * HH * 2049]; // rfft(pd, 4096)
__device__ float  g_dCt [HH * CCHN * LL];     // (H,C,L)
__device__ float  g_part[CSPLIT * NBATCH * HH * LL]; // conv partial sums (33.6 MB)

__device__ __forceinline__ float2 cmulf(float2 a, float2 b) {
    return make_float2(a.x * b.x - a.y * b.y, a.x * b.y + a.y * b.x);
}
__device__ __forceinline__ float2 caddf(float2 a, float2 b) { return make_float2(a.x + b.x, a.y + b.y); }
__device__ __forceinline__ float2 csubf(float2 a, float2 b) { return make_float2(a.x - b.x, a.y - b.y); }

// ---- packed f32x2 helpers (sm_103a FFMA2 path, PTX-only) ----
__device__ __forceinline__ unsigned long long fma2(unsigned long long a, unsigned long long b,
                                                   unsigned long long c) {
    unsigned long long d;
    asm("fma.rn.f32x2 %0, %1, %2, %3;" : "=l"(d) : "l"(a), "l"(b), "l"(c));
    return d;
}
__device__ __forceinline__ unsigned long long pack2(float lo, float hi) {
    unsigned long long r;
    asm("mov.b64 %0, {%1, %2};" : "=l"(r) : "f"(lo), "f"(hi));
    return r;
}
__device__ __forceinline__ void unpack2(unsigned long long v, float& lo, float& hi) {
    asm("mov.b64 {%0, %1}, %2;" : "=f"(lo), "=f"(hi) : "l"(v));
}

__global__ void k_init_tw() {
    int i = blockIdx.x * blockDim.x + threadIdx.x;
    if (i < 2048) {
        double a = -M_PI * (double)i / 2048.0;
        g_tw[i] = make_float2((float)cos(a), (float)sin(a));
    }
}

// ---------------- dC transpose: (L,H,C) -> (H,C,L) ----------------
__global__ void k_transpose(const float* __restrict__ dC) {
    __shared__ float t[32][33];
    int h  = blockIdx.y;
    int l0 = blockIdx.x * 32;
    int tid = threadIdx.x;
    int c = tid & 31, r = tid >> 5;
    for (int i = r; i < 32; i += 8)
        t[i][c] = dC[(size_t)(l0 + i) * (HH * NN) + h * NN + c];
    __syncthreads();
    int li = tid & 31, cc = tid >> 5;
    for (int i = cc; i < 32; i += 8)
        g_dCt[((size_t)h * CCHN + i) * LL + l0 + li] = t[li][i];
}

// ---------------- small DFTs in registers ----------------
__device__ __forceinline__ void dft4(float2& a, float2& b, float2& c, float2& d, int inv) {
    float2 A = caddf(a, c), B = csubf(a, c), C = caddf(b, d), D = csubf(b, d);
    a = caddf(A, C); c = csubf(A, C);
    if (!inv) { b = make_float2(B.x + D.y, B.y - D.x); d = make_float2(B.x - D.y, B.y + D.x); }
    else      { b = make_float2(B.x - D.y, B.y + D.x); d = make_float2(B.x + D.y, B.y - D.x); }
}

__device__ __forceinline__ void dft8(float2 x[8], int inv) {
    float2 e0 = x[0], e1 = x[2], e2 = x[4], e3 = x[6];
    float2 o0 = x[1], o1 = x[3], o2 = x[5], o3 = x[7];
    dft4(e0, e1, e2, e3, inv);
    dft4(o0, o1, o2, o3, inv);
    const float r = 0.70710678118654752f;
    float sg = inv ? 1.f : -1.f;
    float2 w1 = make_float2(r, sg * r);
    float2 w2 = make_float2(0.f, sg);
    float2 w3 = make_float2(-r, sg * r);
    o1 = cmulf(o1, w1); o2 = cmulf(o2, w2); o3 = cmulf(o3, w3);
    x[0] = caddf(e0, o0); x[4] = csubf(e0, o0);
    x[1] = caddf(e1, o1); x[5] = csubf(e1, o1);
    x[2] = caddf(e2, o2); x[6] = csubf(e2, o2);
    x[3] = caddf(e3, o3); x[7] = csubf(e3, o3);
}

// 16-pt DFT; output X[k1+4k2] lands at x[4*k1+k2] (use perm on store)
__device__ __forceinline__ void dft16(float2 x[16], int inv) {
    #pragma unroll
    for (int n1 = 0; n1 < 4; ++n1)
        dft4(x[n1], x[n1 + 4], x[n1 + 8], x[n1 + 12], inv);
    const float c1 = 0.92387953251128675f, s1 = 0.38268343236508977f, r = 0.70710678118654752f;
    float sg = inv ? 1.f : -1.f;
    float2 W1 = make_float2(c1,  sg * s1);
    float2 W2 = make_float2(r,   sg * r);
    float2 W3 = make_float2(s1,  sg * c1);
    float2 W4 = make_float2(0.f, sg);
    float2 W6 = make_float2(-r,  sg * r);
    float2 W9 = make_float2(-c1, -sg * s1);
    x[5]  = cmulf(x[5],  W1);
    x[9]  = cmulf(x[9],  W2);
    x[13] = cmulf(x[13], W3);
    x[6]  = cmulf(x[6],  W2);
    x[10] = cmulf(x[10], W4);
    x[14] = cmulf(x[14], W6);
    x[7]  = cmulf(x[7],  W3);
    x[11] = cmulf(x[11], W6);
    x[15] = cmulf(x[15], W9);
    #pragma unroll
    for (int k1 = 0; k1 < 4; ++k1)
        dft4(x[4 * k1], x[4 * k1 + 1], x[4 * k1 + 2], x[4 * k1 + 3], inv);
}

// ---------------- 2048-pt FFT, 128 threads per sub-FFT, radix 16/16/8 ----------------
template <int INV, int PREMOD>
__device__ void fft2048(float* re, float* im, int u, float scale = 1.0f) {
    float2 x[16];
    __syncthreads();
    #pragma unroll
    for (int m = 0; m < 16; ++m) {
        int a = u + 128 * m, i = PIX(a);
        float2 v = make_float2(re[i], im[i]);
        if (PREMOD) {
            float2 w = g_tw[a];
            v = make_float2(scale * (v.x * w.x - v.y * w.y),
                            scale * (v.x * w.y + v.y * w.x));
        }
        x[m] = v;
    }
    dft16(x, INV);
    __syncthreads();
    #pragma unroll
    for (int m = 0; m < 16; ++m) {
        int d = 16 * u + m, i = PIX(d);
        float2 v = x[((m & 3) << 2) | (m >> 2)];
        re[i] = v.x; im[i] = v.y;
    }
    __syncthreads();
    #pragma unroll
    for (int m = 0; m < 16; ++m) { int a = u + 128 * m, i = PIX(a); x[m] = make_float2(re[i], im[i]); }
    {
        int p = u & 15;
        float2 w = g_tw[16 * p];
        if (INV) w.y = -w.y;
        float2 cur = w;
        #pragma unroll
        for (int m = 1; m < 16; ++m) { x[m] = cmulf(x[m], cur); cur = cmulf(cur, w); }
    }
    dft16(x, INV);
    __syncthreads();
    {
        int base = ((u >> 4) << 8) + (u & 15);
        #pragma unroll
        for (int m = 0; m < 16; ++m) {
            int d = base + 16 * m, i = PIX(d);
            float2 v = x[((m & 3) << 2) | (m >> 2)];
            re[i] = v.x; im[i] = v.y;
        }
    }
    __syncthreads();
    float2 e[8], f[8];
    #pragma unroll
    for (int m = 0; m < 8; ++m) {
        int a0 = u + 256 * m, a1 = u + 128 + 256 * m;
        e[m] = make_float2(re[PIX(a0)], im[PIX(a0)]);
        f[m] = make_float2(re[PIX(a1)], im[PIX(a1)]);
    }
    {
        float2 w0 = g_tw[2 * u], w1 = g_tw[2 * (u + 128)];
        if (INV) { w0.y = -w0.y; w1.y = -w1.y; }
        float2 c0 = w0, c1 = w1;
        #pragma unroll
        for (int m = 1; m < 8; ++m) {
            e[m] = cmulf(e[m], c0); c0 = cmulf(c0, w0);
            f[m] = cmulf(f[m], c1); c1 = cmulf(c1, w1);
        }
    }
    dft8(e, INV); dft8(f, INV);
    __syncthreads();
    #pragma unroll
    for (int m = 0; m < 8; ++m) {
        int d0 = u + 256 * m, d1 = u + 128 + 256 * m;
        re[PIX(d0)] = e[m].x; im[PIX(d0)] = e[m].y;
        re[PIX(d1)] = f[m].x; im[PIX(d1)] = f[m].y;
    }
    __syncthreads();
}

// ---------------- Cauchy + Woodbury -> k_f (C,H,1025) ----------------
// 2 l-values x 8 channels per thread: LDS.128 per FFMA2 halved, 2x ILP.
// lb in [0,512): handles l=lb and l=lb+512; lb==512: Nyquist l=1024.
__global__ __launch_bounds__(128, 4) void k_cauchy(
    const float* __restrict__ log_dt, const float* __restrict__ B_ri,
    const float* __restrict__ P_ri,   const float* __restrict__ C_ri,
    const float* __restrict__ iwr,    const float* __restrict__ wim) {
    int h   = blockIdx.y;
    int c0  = blockIdx.z * 8;
    int tid = threadIdx.x;
    int lb  = blockIdx.x * blockDim.x + tid;

    __shared__ float2 sB[NN], sP[NN], sW[NN];
    __shared__ float4 sC4[8][NN];               // (Cx, Cx, Cy, Cy)

    float dt = expf(log_dt[h]);
    if (tid < NN) {
        sB[tid] = ((const float2*)B_ri)[h * NN + tid];
        sP[tid] = ((const float2*)P_ri)[h * NN + tid];
        sW[tid] = make_float2(-expf(iwr[h * NN + tid]) * dt,
                              wim[h * NN + tid] * dt);
    }
    if (tid < 8 * NN - 128) { /* nothing: 256 entries loaded below */ }
    for (int i = tid; i < 8 * NN; i += blockDim.x) {
        int j = i / NN, n = i % NN;
        float2 C = ((const float2*)C_ri)[(c0 + j) * (HH * NN) + h * NN + n];
        sC4[j][n] = make_float4(C.x, C.x, C.y, C.y);
    }
    __syncthreads();

    if (lb > 512) return;

    if (lb == 512) {
        // analytic Nyquist limit at l=1024: k_f[c] = dt * Re(sum_n B[n]*C[c][n])
        #pragma unroll
        for (int j = 0; j < 8; ++j) {
            float acc = 0.f;
            #pragma unroll
            for (int n = 0; n < NN; ++n)
                acc += sB[n].x * sC4[j][n].x - sB[n].y * sC4[j][n].z;
            g_kf[((c0 + j) * HH + h) * LF + 1024] = make_float2(dt * acc, 0.f);
        }
        return;
    }

    int l1 = lb, l2 = lb + 512;
    float2 z1, fac1, z2, fac2;
    {
        float s, cg;
        sincospif((float)l1 * (1.0f / 1024.0f), &s, &cg);
        float2 om  = make_float2(cg, -s);
        float2 den = make_float2(1.f + om.x, om.y);
        float  dn  = den.x * den.x + den.y * den.y;
        float2 num = make_float2(1.f - om.x, -om.y);
        z1   = make_float2(2.f * (num.x * den.x + num.y * den.y) / dn,
                           2.f * (num.y * den.x - num.x * den.y) / dn);
        fac1 = make_float2(2.f * den.x / dn, -2.f * den.y / dn);
        sincospif((float)l2 * (1.0f / 1024.0f), &s, &cg);
        om  = make_float2(cg, -s);
        den = make_float2(1.f + om.x, om.y);
        dn  = den.x * den.x + den.y * den.y;
        num = make_float2(1.f - om.x, -om.y);
        z2   = make_float2(2.f * (num.x * den.x + num.y * den.y) / dn,
                           2.f * (num.y * den.x - num.x * den.y) / dn);
        fac2 = make_float2(2.f * den.x / dn, -2.f * den.y / dn);
    }

    unsigned long long A0a[8], A1a[8], A0b[8], A1b[8];
    unsigned long long A0qa = 0ULL, A1qa = 0ULL, A0qb = 0ULL, A1qb = 0ULL;
    #pragma unroll
    for (int j = 0; j < 8; ++j) { A0a[j] = 0ULL; A1a[j] = 0ULL; A0b[j] = 0ULL; A1b[j] = 0ULL; }

    #pragma unroll
    for (int n = 0; n < NN; ++n) {
        float2 w  = sW[n];
        float2 Bn = sB[n], Pn = sP[n];
        unsigned long long cxxq = pack2(Pn.x, Pn.x);
        unsigned long long cyyq = pack2(-Pn.y, -Pn.y);

        unsigned long long S0a, D0a, S1a, D1a;
        {
            float2 u = make_float2(z1.x - w.x, z1.y - w.y);
            float iu = 1.f / (u.x * u.x + u.y * u.y);
            float2 cp = make_float2(u.x * iu, -u.y * iu);
            float2 v = make_float2(z1.x - w.x, z1.y + w.y);
            float iv = 1.f / (v.x * v.x + v.y * v.y);
            float2 cm = make_float2(v.x * iv, -v.y * iv);
            float2 ap0 = cmulf(Bn, cp);
            float2 am0 = cmulf(make_float2(Bn.x, -Bn.y), cm);
            float2 ap1 = cmulf(Pn, cp);
            float2 am1 = cmulf(make_float2(Pn.x, -Pn.y), cm);
            float2 s0 = caddf(ap0, am0), d0 = csubf(ap0, am0);
            float2 s1 = caddf(ap1, am1), d1 = csubf(ap1, am1);
            S0a = pack2(s0.x, s0.y); D0a = pack2(-d0.y, d0.x);
            S1a = pack2(s1.x, s1.y); D1a = pack2(-d1.y, d1.x);
        }
        unsigned long long S0b, D0b, S1b, D1b;
        {
            float2 u = make_float2(z2.x - w.x, z2.y - w.y);
            float iu = 1.f / (u.x * u.x + u.y * u.y);
            float2 cp = make_float2(u.x * iu, -u.y * iu);
            float2 v = make_float2(z2.x - w.x, z2.y + w.y);
            float iv = 1.f / (v.x * v.x + v.y * v.y);
            float2 cm = make_float2(v.x * iv, -v.y * iv);
            float2 ap0 = cmulf(Bn, cp);
            float2 am0 = cmulf(make_float2(Bn.x, -Bn.y), cm);
            float2 ap1 = cmulf(Pn, cp);
            float2 am1 = cmulf(make_float2(Pn.x, -Pn.y), cm);
            float2 s0 = caddf(ap0, am0), d0 = csubf(ap0, am0);
            float2 s1 = caddf(ap1, am1), d1 = csubf(ap1, am1);
            S0b = pack2(s0.x, s0.y); D0b = pack2(-d0.y, d0.x);
            S1b = pack2(s1.x, s1.y); D1b = pack2(-d1.y, d1.x);
        }
        #pragma unroll
        for (int j = 0; j < 8; ++j) {
            union { float4 f; unsigned long long u64[2]; } cc;
            cc.f = sC4[j][n];
            A0a[j] = fma2(cc.u64[0], S0a, A0a[j]);
            A0a[j] = fma2(cc.u64[1], D0a, A0a[j]);
            A1a[j] = fma2(cc.u64[0], S1a, A1a[j]);
            A1a[j] = fma2(cc.u64[1], D1a, A1a[j]);
            A0b[j] = fma2(cc.u64[0], S0b, A0b[j]);
            A0b[j] = fma2(cc.u64[1], D0b, A0b[j]);
            A1b[j] = fma2(cc.u64[0], S1b, A1b[j]);
            A1b[j] = fma2(cc.u64[1], D1b, A1b[j]);
        }
        A0qa = fma2(cxxq, S0a, A0qa); A0qa = fma2(cyyq, D0a, A0qa);
        A1qa = fma2(cxxq, S1a, A1qa); A1qa = fma2(cyyq, D1a, A1qa);
        A0qb = fma2(cxxq, S0b, A0qb); A0qb = fma2(cyyq, D0b, A0qb);
        A1qb = fma2(cxxq, S1b, A1qb); A1qb = fma2(cyyq, D1b, A1qb);
    }

    // Woodbury + store, l1 then l2
    {
        float2 r0q, r1q;
        unpack2(A0qa, r0q.x, r0q.y);
        unpack2(A1qa, r1q.x, r1q.y);
        r0q.x *= dt; r0q.y *= dt; r1q.x *= dt; r1q.y *= dt;
        float2 onep = make_float2(1.f + r1q.x, r1q.y);
        float  oin  = 1.f / (onep.x * onep.x + onep.y * onep.y);
        float2 coef = cmulf(r0q, make_float2(onep.x * oin, -onep.y * oin));
        #pragma unroll
        for (int j = 0; j < 8; ++j) {
            float2 a0j, a1j;
            unpack2(A0a[j], a0j.x, a0j.y);
            unpack2(A1a[j], a1j.x, a1j.y);
            float2 R0 = make_float2(a0j.x * dt, a0j.y * dt);
            float2 R1 = make_float2(a1j.x * dt, a1j.y * dt);
            float2 corr = cmulf(coef, R1);
            g_kf[((c0 + j) * HH + h) * LF + l1] = cmulf(csubf(R0, corr), fac1);
        }
    }
    {
        float2 r0q, r1q;
        unpack2(A0qb, r0q.x, r0q.y);
        unpack2(A1qb, r1q.x, r1q.y);
        r0q.x *= dt; r0q.y *= dt; r1q.x *= dt; r1q.y *= dt;
        float2 onep = make_float2(1.f + r1q.x, r1q.y);
        float  oin  = 1.f / (onep.x * onep.x + onep.y * onep.y);
        float2 coef = cmulf(r0q, make_float2(onep.x * oin, -onep.y * oin));
        #pragma unroll
        for (int j = 0; j < 8; ++j) {
            float2 a0j, a1j;
            unpack2(A0b[j], a0j.x, a0j.y);
            unpack2(A1b[j], a1j.x, a1j.y);
            float2 R0 = make_float2(a0j.x * dt, a0j.y * dt);
            float2 R1 = make_float2(a1j.x * dt, a1j.y * dt);
            float2 corr = cmulf(coef, R1);
            g_kf[((c0 + j) * HH + h) * LF + l2] = cmulf(csubf(R0, corr), fac2);
        }
    }
}

// ---------------- 4096-DFT of the kernel: unified even+odd spectrum to g_k4 ----------------
__global__ __launch_bounds__(256, 3) void k_kernelfft() {
    __shared__ float sre[2 * PADN], sim[2 * PADN];
    int s = threadIdx.x >> 7, u = threadIdx.x & 127;
    int p = blockIdx.x * 2 + s;                       // pair index in [0, 4096)
    int c1 = (p >> 8) * 2;                            // even channel
    int h  = p & 255;
    int ch1 = c1 * HH + h;
    int ch2 = ch1 + HH;                               // channel c1+1, same h
    float* re = sre + s * PADN;
    float* im = sim + s * PADN;

    const float2* kf1 = g_kf + (size_t)ch1 * LF;
    const float2* kf2 = g_kf + (size_t)ch2 * LF;
    float2* o1 = g_k4 + (size_t)ch1 * 2049;
    float2* o2 = g_k4 + (size_t)ch2 * 2049;
    for (int i = u; i <= 1024; i += 128) {
        float2 X1 = kf1[i];
        float2 X2 = kf2[i];
        o1[2 * i] = X1;                               // even bins of 4096-DFT
        o2[2 * i] = X2;
        re[PIX(i)] = X1.x - X2.y;                     // Z = X1 + i*X2
        im[PIX(i)] = X1.y + X2.x;
        if (i >= 1 && i < 1024) {
            int m = 2048 - i;                         // conj(X1) + i*conj(X2)
            re[PIX(m)] = X1.x + X2.y;
            im[PIX(m)] = X2.x - X1.y;
        }
    }
    fft2048<1, 0>(re, im, u);                         // z = (k1 + i*k2) * 2048
    fft2048<0, 1>(re, im, u, 1.0f / 2048.0f);         // Y = FFT(z/2048 * e^{-i*pi*l/2048})
    for (int j = u; j < 1024; j += 128) {
        int pj = PIX(j), pm = PIX(2047 - j);
        float Pr = re[pj], Pi = im[pj];
        float Mr = re[pm], Mi = im[pm];
        o1[2 * j + 1] = make_float2(0.5f * (Pr + Mr), 0.5f * (Pi - Mi));
        o2[2 * j + 1] = make_float2(0.5f * (Pi + Mi), 0.5f * (Mr - Pr));
    }
}

// ---------------- rfft(pd, 4096) via real packing (2 rows/block) ----------------
__global__ __launch_bounds__(256, 3) void k_pdfft(const float* __restrict__ pd) {
    __shared__ float sre[2 * PADN], sim[2 * PADN];
    int s = threadIdx.x >> 7, u = threadIdx.x & 127;
    int ch = blockIdx.x * 2 + s;                      // b*256 + h
    float* re = sre + s * PADN;
    float* im = sim + s * PADN;

    const float* src = pd + (size_t)ch * LL;
    for (int n = u; n < 2048; n += 128) {
        if (n < 1024) { re[PIX(n)] = src[2 * n]; im[PIX(n)] = src[2 * n + 1]; }
        else          { re[PIX(n)] = 0.f;        im[PIX(n)] = 0.f; }
    }
    fft2048<0, 0>(re, im, u);
    float2* dst = g_pdf + (size_t)ch * 2049;
    for (int k = u; k < 2048; k += 128) {
        float2 Yk = make_float2(re[PIX(k)], im[PIX(k)]);
        int km = (2048 - k) & 2047;
        float2 Ym = make_float2(re[PIX(km)], im[PIX(km)]);
        float2 E = make_float2(0.5f * (Yk.x + Ym.x), 0.5f * (Yk.y - Ym.y));
        float2 D = make_float2(Yk.x - Ym.x, Yk.y + Ym.y);
        float2 O = make_float2(0.5f * D.y, -0.5f * D.x);
        float2 w = g_tw[k];
        dst[k] = caddf(E, cmulf(w, O));
    }
    if (u == 0) {
        float2 Y0 = make_float2(re[PIX(0)], im[PIX(0)]);
        dst[2048] = make_float2(Y0.x - Y0.y, 0.f);
    }
}

// ---------------- conv: grid (HH, CSPLIT); 4 channel iters x 2 batches; partials to g_part ----------------
__global__ __launch_bounds__(256, 3) void k_conv() {
    extern __shared__ char smraw[];
    float*  sre = (float*)smraw;                 // 2*PADN
    float*  sim = sre + 2 * PADN;                // 2*PADN
    float2* sPD = (float2*)(sim + 2 * PADN);     // 2*2049
    int tid = threadIdx.x, s = tid >> 7, u = tid & 127;   // s = batch
    int h = blockIdx.x;
    int split = blockIdx.y;
    float* re = sre + s * PADN;
    float* im = sim + s * PADN;

    for (int b = 0; b < NBATCH; ++b) {
        const float2* pf = g_pdf + ((size_t)b * HH + h) * 2049;
        for (int m = tid; m < 2049; m += 256) sPD[b * 2049 + m] = pf[m];
    }
    float racc0[8], racc1[8];
    #pragma unroll
    for (int i = 0; i < 8; ++i) { racc0[i] = 0.f; racc1[i] = 0.f; }
    __syncthreads();

    const float2* sPDs = sPD + s * 2049;
    int cbeg = split * (CCHN / CSPLIT);
    for (int ci = 0; ci < CCHN / CSPLIT; ++ci) {
        int c = cbeg + ci;
        const float2* kp = g_k4 + ((size_t)c * HH + h) * 2049;
        for (int k = u; k < 2048; k += 128) {
            float2 Ka = kp[k];
            float2 Kb = kp[2048 - k];
            float2 Xk = cmulf(sPDs[k],        Ka);
            float2 X2 = cmulf(sPDs[2048 - k], Kb);
            float2 E = make_float2(0.5f * (Xk.x + X2.x), 0.5f * (Xk.y - X2.y));
            float2 D = make_float2(Xk.x - X2.x, Xk.y + X2.y);
            float2 w = g_tw[k];
            float2 O = make_float2(0.5f * (D.x * w.x + D.y * w.y),
                                   0.5f * (D.y * w.x - D.x * w.y));   // (D/2)*conj(w)
            re[PIX(k)] = E.x - O.y;                                   // Y = E + i*O
            im[PIX(k)] = E.y + O.x;
        }
        fft2048<1, 0>(re, im, u);
        const float* wv = g_dCt + ((size_t)h * CCHN + c) * LL;
        #pragma unroll
        for (int i = 0; i < 8; ++i) {
            int l = tid + 256 * i;
            int pi = PIX(l >> 1);
            float wl = (1.0f / 2048.0f) * wv[l];
            float x0 = (l & 1) ? sim[pi] : sre[pi];
            float x1 = (l & 1) ? sim[PADN + pi] : sre[PADN + pi];
            racc0[i] += x0 * wl;
            racc1[i] += x1 * wl;
        }
        __syncthreads();
    }
    float* p0 = g_part + (((size_t)split * NBATCH + 0) * HH + h) * LL;
    float* p1 = g_part + (((size_t)split * NBATCH + 1) * HH + h) * LL;
    #pragma unroll
    for (int i = 0; i < 8; ++i) {
        int l = tid + 256 * i;
        p0[l] = racc0[i];
        p1[l] = racc1[i];
    }
}

// ---------------- reduce partials -> out ----------------
__global__ void k_reduce(float* __restrict__ out) {
    int i = blockIdx.x * blockDim.x + threadIdx.x;     // over NBATCH*HH*LL
    const int TOT = NBATCH * HH * LL;
    if (i >= TOT) return;
    float v = 0.f;
    #pragma unroll
    for (int sp = 0; sp < CSPLIT; ++sp)
        v += g_part[(size_t)sp * TOT + i];
    out[i] = v;
}

// ---------------- launch ----------------
extern "C" void kernel_launch(void* const* d_in, const int* in_sizes, int n_in,
                              void* d_out, int out_size) {
    const float* log_dt = (const float*)d_in[0];
    const float* B_ri   = (const float*)d_in[1];
    const float* P_ri   = (const float*)d_in[2];
    const float* C_ri   = (const float*)d_in[3];
    const float* iwr    = (const float*)d_in[4];
    const float* wim    = (const float*)d_in[5];
    const float* dC     = (const float*)d_in[6];
    const float* pd     = (const float*)d_in[7];
    float* out = (float*)d_out;
    (void)in_sizes; (void)n_in; (void)out_size;

    const int SM_CONV = (2 * PADN * 2) * (int)sizeof(float)       // sre+sim
                      + 2 * 2049 * (int)sizeof(float2);           // sPD both batches
    cudaFuncSetAttribute(k_conv, cudaFuncAttributeMaxDynamicSharedMemorySize, SM_CONV);

    k_init_tw<<<8, 256>>>();
    k_transpose<<<dim3(LL / 32, HH), 256>>>(dC);
    k_cauchy<<<dim3((513 + 127) / 128, HH, 4), 128>>>(log_dt, B_ri, P_ri, C_ri, iwr, wim);
    k_kernelfft<<<CCHN * HH / 4, 256>>>();
    k_pdfft<<<NBATCH * HH / 2, 256>>>(pd);
    k_conv<<<dim3(HH, CSPLIT), 256, SM_CONV>>>();
    k_reduce<<<(NBATCH * HH * LL + 255) / 256, 256>>>(out);
}

// round 13
// speedup vs baseline: 1.1720x; 1.1720x over previous
#include <cuda_runtime.h>
#include <math.h>

#define HH 256
#define NN 32
#define CCHN 32
#define LL 2048
#define LF 1025
#define NBATCH 2
#define CSPLIT 8
#define PADN 2176                       // 2048 + 128 pad floats
#define PIX(a) ((a) + ((a) >> 4))

// ---------------- scratch ----------------
__device__ float2 g_tw[2048];                 // e^{-2*pi*i*k/4096}
__device__ float2 g_kf  [CCHN * HH * LF];     // (C,H,1025) 2048-DFT of kernel (= even bins of 4096-DFT)
__device__ float2 g_kodd[CCHN * HH * 1024];   // odd bins of 4096-DFT
__device__ float2 g_pdf [NBATCH * HH * 2049]; // rfft(pd, 4096)
__device__ float  g_dCt [HH * CCHN * LL];     // (H,C,L)
__device__ float  g_part[CSPLIT * NBATCH * HH * LL]; // conv partial sums (33.6 MB)

__device__ __forceinline__ float2 cmulf(float2 a, float2 b) {
    return make_float2(a.x * b.x - a.y * b.y, a.x * b.y + a.y * b.x);
}
__device__ __forceinline__ float2 caddf(float2 a, float2 b) { return make_float2(a.x + b.x, a.y + b.y); }
__device__ __forceinline__ float2 csubf(float2 a, float2 b) { return make_float2(a.x - b.x, a.y - b.y); }

// ---- packed f32x2 helpers (sm_103a FFMA2 path, PTX-only) ----
__device__ __forceinline__ unsigned long long fma2(unsigned long long a, unsigned long long b,
                                                   unsigned long long c) {
    unsigned long long d;
    asm("fma.rn.f32x2 %0, %1, %2, %3;" : "=l"(d) : "l"(a), "l"(b), "l"(c));
    return d;
}
__device__ __forceinline__ unsigned long long pack2(float lo, float hi) {
    unsigned long long r;
    asm("mov.b64 %0, {%1, %2};" : "=l"(r) : "f"(lo), "f"(hi));
    return r;
}
__device__ __forceinline__ void unpack2(unsigned long long v, float& lo, float& hi) {
    asm("mov.b64 {%0, %1}, %2;" : "=f"(lo), "=f"(hi) : "l"(v));
}

__global__ void k_init_tw() {
    int i = blockIdx.x * blockDim.x + threadIdx.x;
    if (i < 2048) {
        double a = -M_PI * (double)i / 2048.0;
        g_tw[i] = make_float2((float)cos(a), (float)sin(a));
    }
}

// ---------------- dC transpose: (L,H,C) -> (H,C,L) ----------------
__global__ void k_transpose(const float* __restrict__ dC) {
    __shared__ float t[32][33];
    int h  = blockIdx.y;
    int l0 = blockIdx.x * 32;
    int tid = threadIdx.x;
    int c = tid & 31, r = tid >> 5;
    for (int i = r; i < 32; i += 8)
        t[i][c] = dC[(size_t)(l0 + i) * (HH * NN) + h * NN + c];
    __syncthreads();
    int li = tid & 31, cc = tid >> 5;
    for (int i = cc; i < 32; i += 8)
        g_dCt[((size_t)h * CCHN + i) * LL + l0 + li] = t[li][i];
}

// ---------------- small DFTs in registers ----------------
__device__ __forceinline__ void dft4(float2& a, float2& b, float2& c, float2& d, int inv) {
    float2 A = caddf(a, c), B = csubf(a, c), C = caddf(b, d), D = csubf(b, d);
    a = caddf(A, C); c = csubf(A, C);
    if (!inv) { b = make_float2(B.x + D.y, B.y - D.x); d = make_float2(B.x - D.y, B.y + D.x); }
    else      { b = make_float2(B.x - D.y, B.y + D.x); d = make_float2(B.x + D.y, B.y - D.x); }
}

__device__ __forceinline__ void dft8(float2 x[8], int inv) {
    float2 e0 = x[0], e1 = x[2], e2 = x[4], e3 = x[6];
    float2 o0 = x[1], o1 = x[3], o2 = x[5], o3 = x[7];
    dft4(e0, e1, e2, e3, inv);
    dft4(o0, o1, o2, o3, inv);
    const float r = 0.70710678118654752f;
    float sg = inv ? 1.f : -1.f;
    float2 w1 = make_float2(r, sg * r);
    float2 w2 = make_float2(0.f, sg);
    float2 w3 = make_float2(-r, sg * r);
    o1 = cmulf(o1, w1); o2 = cmulf(o2, w2); o3 = cmulf(o3, w3);
    x[0] = caddf(e0, o0); x[4] = csubf(e0, o0);
    x[1] = caddf(e1, o1); x[5] = csubf(e1, o1);
    x[2] = caddf(e2, o2); x[6] = csubf(e2, o2);
    x[3] = caddf(e3, o3); x[7] = csubf(e3, o3);
}

// 16-pt DFT; output X[k1+4k2] lands at x[4*k1+k2] (use perm on store)
__device__ __forceinline__ void dft16(float2 x[16], int inv) {
    #pragma unroll
    for (int n1 = 0; n1 < 4; ++n1)
        dft4(x[n1], x[n1 + 4], x[n1 + 8], x[n1 + 12], inv);
    const float c1 = 0.92387953251128675f, s1 = 0.38268343236508977f, r = 0.70710678118654752f;
    float sg = inv ? 1.f : -1.f;
    float2 W1 = make_float2(c1,  sg * s1);
    float2 W2 = make_float2(r,   sg * r);
    float2 W3 = make_float2(s1,  sg * c1);
    float2 W4 = make_float2(0.f, sg);
    float2 W6 = make_float2(-r,  sg * r);
    float2 W9 = make_float2(-c1, -sg * s1);
    x[5]  = cmulf(x[5],  W1);
    x[9]  = cmulf(x[9],  W2);
    x[13] = cmulf(x[13], W3);
    x[6]  = cmulf(x[6],  W2);
    x[10] = cmulf(x[10], W4);
    x[14] = cmulf(x[14], W6);
    x[7]  = cmulf(x[7],  W3);
    x[11] = cmulf(x[11], W6);
    x[15] = cmulf(x[15], W9);
    #pragma unroll
    for (int k1 = 0; k1 < 4; ++k1)
        dft4(x[4 * k1], x[4 * k1 + 1], x[4 * k1 + 2], x[4 * k1 + 3], inv);
}

// ---------------- 2048-pt FFT, 128 threads per sub-FFT, radix 16/16/8 ----------------
// PREMOD: stage-0 load multiplies by scale*g_tw[a] (fuses the modulate pass).
template <int INV, int PREMOD>
__device__ void fft2048(float* re, float* im, int u, float scale = 1.0f) {
    float2 x[16];
    __syncthreads();
    #pragma unroll
    for (int m = 0; m < 16; ++m) {
        int a = u + 128 * m, i = PIX(a);
        float2 v = make_float2(re[i], im[i]);
        if (PREMOD) {
            float2 w = g_tw[a];
            v = make_float2(scale * (v.x * w.x - v.y * w.y),
                            scale * (v.x * w.y + v.y * w.x));
        }
        x[m] = v;
    }
    dft16(x, INV);
    __syncthreads();
    #pragma unroll
    for (int m = 0; m < 16; ++m) {
        int d = 16 * u + m, i = PIX(d);
        float2 v = x[((m & 3) << 2) | (m >> 2)];
        re[i] = v.x; im[i] = v.y;
    }
    __syncthreads();
    #pragma unroll
    for (int m = 0; m < 16; ++m) { int a = u + 128 * m, i = PIX(a); x[m] = make_float2(re[i], im[i]); }
    {
        int p = u & 15;
        float2 w = g_tw[16 * p];
        if (INV) w.y = -w.y;
        float2 cur = w;
        #pragma unroll
        for (int m = 1; m < 16; ++m) { x[m] = cmulf(x[m], cur); cur = cmulf(cur, w); }
    }
    dft16(x, INV);
    __syncthreads();
    {
        int base = ((u >> 4) << 8) + (u & 15);
        #pragma unroll
        for (int m = 0; m < 16; ++m) {
            int d = base + 16 * m, i = PIX(d);
            float2 v = x[((m & 3) << 2) | (m >> 2)];
            re[i] = v.x; im[i] = v.y;
        }
    }
    __syncthreads();
    float2 e[8], f[8];
    #pragma unroll
    for (int m = 0; m < 8; ++m) {
        int a0 = u + 256 * m, a1 = u + 128 + 256 * m;
        e[m] = make_float2(re[PIX(a0)], im[PIX(a0)]);
        f[m] = make_float2(re[PIX(a1)], im[PIX(a1)]);
    }
    {
        float2 w0 = g_tw[2 * u], w1 = g_tw[2 * (u + 128)];
        if (INV) { w0.y = -w0.y; w1.y = -w1.y; }
        float2 c0 = w0, c1 = w1;
        #pragma unroll
        for (int m = 1; m < 8; ++m) {
            e[m] = cmulf(e[m], c0); c0 = cmulf(c0, w0);
            f[m] = cmulf(f[m], c1); c1 = cmulf(c1, w1);
        }
    }
    dft8(e, INV); dft8(f, INV);
    __syncthreads();
    #pragma unroll
    for (int m = 0; m < 8; ++m) {
        int d0 = u + 256 * m, d1 = u + 128 + 256 * m;
        re[PIX(d0)] = e[m].x; im[PIX(d0)] = e[m].y;
        re[PIX(d1)] = f[m].x; im[PIX(d1)] = f[m].y;
    }
    __syncthreads();
}

// ---------------- Cauchy + Woodbury -> k_f (C,H,1025) ----------------
// R11-proven: single n-loop; 16 channels per thread (blockIdx.z picks half); FFMA2 inner loop.
__global__ __launch_bounds__(128, 4) void k_cauchy(
    const float* __restrict__ log_dt, const float* __restrict__ B_ri,
    const float* __restrict__ P_ri,   const float* __restrict__ C_ri,
    const float* __restrict__ iwr,    const float* __restrict__ wim) {
    int h    = blockIdx.y;
    int half = blockIdx.z;
    int c0   = half * 16;
    int tid  = threadIdx.x;
    int l    = blockIdx.x * blockDim.x + tid;

    __shared__ float2 sB[NN], sP[NN], sW[NN];
    __shared__ float4 sC4[16][NN];              // (Cx, Cx, Cy, Cy)

    float dt = expf(log_dt[h]);
    if (tid < NN) {
        sB[tid] = ((const float2*)B_ri)[h * NN + tid];
        sP[tid] = ((const float2*)P_ri)[h * NN + tid];
        sW[tid] = make_float2(-expf(iwr[h * NN + tid]) * dt,
                              wim[h * NN + tid] * dt);
    }
    for (int i = tid; i < 16 * NN; i += blockDim.x) {
        int j = i / NN, n = i % NN;
        float2 C = ((const float2*)C_ri)[(c0 + j) * (HH * NN) + h * NN + n];
        sC4[j][n] = make_float4(C.x, C.x, C.y, C.y);
    }
    __syncthreads();

    if (l >= LF) return;

    if (l == LL / 2) {
        #pragma unroll
        for (int j = 0; j < 16; ++j) {
            float acc = 0.f;
            #pragma unroll
            for (int n = 0; n < NN; ++n)
                acc += sB[n].x * sC4[j][n].x - sB[n].y * sC4[j][n].z;
            g_kf[((c0 + j) * HH + h) * LF + l] = make_float2(dt * acc, 0.f);
        }
        return;
    }

    float s, cg;
    sincospif((float)l * (1.0f / 1024.0f), &s, &cg);
    float2 om  = make_float2(cg, -s);
    float2 den = make_float2(1.f + om.x, om.y);
    float  dn  = den.x * den.x + den.y * den.y;
    float2 num = make_float2(1.f - om.x, -om.y);
    float2 z   = make_float2(2.f * (num.x * den.x + num.y * den.y) / dn,
                             2.f * (num.y * den.x - num.x * den.y) / dn);
    float2 fac = make_float2(2.f * den.x / dn, -2.f * den.y / dn);

    unsigned long long A0[16], A1[16];
    unsigned long long A0q = 0ULL, A1q = 0ULL;
    #pragma unroll
    for (int j = 0; j < 16; ++j) { A0[j] = 0ULL; A1[j] = 0ULL; }

    #pragma unroll
    for (int n = 0; n < NN; ++n) {
        float2 w = sW[n];
        float2 u = make_float2(z.x - w.x, z.y - w.y);
        float iu = 1.f / (u.x * u.x + u.y * u.y);
        float2 cp = make_float2(u.x * iu, -u.y * iu);
        float2 v = make_float2(z.x - w.x, z.y + w.y);
        float iv = 1.f / (v.x * v.x + v.y * v.y);
        float2 cm = make_float2(v.x * iv, -v.y * iv);
        float2 Bn = sB[n], Pn = sP[n];
        float2 ap0 = cmulf(Bn, cp);
        float2 am0 = cmulf(make_float2(Bn.x, -Bn.y), cm);
        float2 ap1 = cmulf(Pn, cp);
        float2 am1 = cmulf(make_float2(Pn.x, -Pn.y), cm);
        float2 s0 = caddf(ap0, am0), d0 = csubf(ap0, am0);
        float2 s1 = caddf(ap1, am1), d1 = csubf(ap1, am1);
        unsigned long long S0 = pack2(s0.x, s0.y);
        unsigned long long D0 = pack2(-d0.y, d0.x);
        unsigned long long S1 = pack2(s1.x, s1.y);
        unsigned long long D1 = pack2(-d1.y, d1.x);
        #pragma unroll
        for (int j = 0; j < 16; ++j) {
            union { float4 f; unsigned long long u64[2]; } cc;
            cc.f = sC4[j][n];
            A0[j] = fma2(cc.u64[0], S0, A0[j]);
            A0[j] = fma2(cc.u64[1], D0, A0[j]);
            A1[j] = fma2(cc.u64[0], S1, A1[j]);
            A1[j] = fma2(cc.u64[1], D1, A1[j]);
        }
        unsigned long long cxxq = pack2(Pn.x, Pn.x);
        unsigned long long cyyq = pack2(-Pn.y, -Pn.y);
        A0q = fma2(cxxq, S0, A0q);
        A0q = fma2(cyyq, D0, A0q);
        A1q = fma2(cxxq, S1, A1q);
        A1q = fma2(cyyq, D1, A1q);
    }

    float2 r0q, r1q;
    unpack2(A0q, r0q.x, r0q.y);
    unpack2(A1q, r1q.x, r1q.y);
    r0q.x *= dt; r0q.y *= dt; r1q.x *= dt; r1q.y *= dt;
    float2 onep = make_float2(1.f + r1q.x, r1q.y);
    float  oin  = 1.f / (onep.x * onep.x + onep.y * onep.y);
    float2 coef = cmulf(r0q, make_float2(onep.x * oin, -onep.y * oin)); // r0q/(1+r1q)

    #pragma unroll
    for (int j = 0; j < 16; ++j) {
        float2 a0j, a1j;
        unpack2(A0[j], a0j.x, a0j.y);
        unpack2(A1[j], a1j.x, a1j.y);
        float2 R0 = make_float2(a0j.x * dt, a0j.y * dt);
        float2 R1 = make_float2(a1j.x * dt, a1j.y * dt);
        float2 corr = cmulf(coef, R1);
        float2 kf = cmulf(csubf(R0, corr), fac);
        g_kf[((c0 + j) * HH + h) * LF + l] = kf;
    }
}

// ---------------- odd bins of the 4096-DFT of the kernel ----------------
// 2-channel complex packing + premod-fused second FFT. (R11-proven)
__global__ __launch_bounds__(256, 3) void k_kernelfft() {
    __shared__ float sre[2 * PADN], sim[2 * PADN];
    int s = threadIdx.x >> 7, u = threadIdx.x & 127;
    int p = blockIdx.x * 2 + s;                       // pair index in [0, 4096)
    int c1 = (p >> 8) * 2;                            // even channel
    int h  = p & 255;
    int ch1 = c1 * HH + h;
    int ch2 = ch1 + HH;                               // channel c1+1, same h
    float* re = sre + s * PADN;
    float* im = sim + s * PADN;

    const float2* kf1 = g_kf + (size_t)ch1 * LF;
    const float2* kf2 = g_kf + (size_t)ch2 * LF;
    for (int i = u; i <= 1024; i += 128) {
        float2 X1 = kf1[i];
        float2 X2 = kf2[i];
        re[PIX(i)] = X1.x - X2.y;                     // Z = X1 + i*X2
        im[PIX(i)] = X1.y + X2.x;
        if (i >= 1 && i < 1024) {
            int m = 2048 - i;                         // conj(X1) + i*conj(X2)
            re[PIX(m)] = X1.x + X2.y;
            im[PIX(m)] = X2.x - X1.y;
        }
    }
    fft2048<1, 0>(re, im, u);                         // z = (k1 + i*k2) * 2048
    fft2048<0, 1>(re, im, u, 1.0f / 2048.0f);         // Y = FFT(z/2048 * e^{-i*pi*l/2048})
    float2* d1 = g_kodd + (size_t)ch1 * 1024;
    float2* d2 = g_kodd + (size_t)ch2 * 1024;
    for (int j = u; j < 1024; j += 128) {
        int pj = PIX(j), pm = PIX(2047 - j);
        float Pr = re[pj], Pi = im[pj];
        float Mr = re[pm], Mi = im[pm];
        d1[j] = make_float2(0.5f * (Pr + Mr), 0.5f * (Pi - Mi));
        d2[j] = make_float2(0.5f * (Pi + Mi), 0.5f * (Mr - Pr));
    }
}

// ---------------- rfft(pd, 4096) via real packing (2 rows/block) ----------------
__global__ __launch_bounds__(256, 3) void k_pdfft(const float* __restrict__ pd) {
    __shared__ float sre[2 * PADN], sim[2 * PADN];
    int s = threadIdx.x >> 7, u = threadIdx.x & 127;
    int ch = blockIdx.x * 2 + s;                      // b*256 + h
    float* re = sre + s * PADN;
    float* im = sim + s * PADN;

    const float* src = pd + (size_t)ch * LL;
    for (int n = u; n < 2048; n += 128) {
        if (n < 1024) { re[PIX(n)] = src[2 * n]; im[PIX(n)] = src[2 * n + 1]; }
        else          { re[PIX(n)] = 0.f;        im[PIX(n)] = 0.f; }
    }
    fft2048<0, 0>(re, im, u);
    float2* dst = g_pdf + (size_t)ch * 2049;
    for (int k = u; k < 2048; k += 128) {
        float2 Yk = make_float2(re[PIX(k)], im[PIX(k)]);
        int km = (2048 - k) & 2047;
        float2 Ym = make_float2(re[PIX(km)], im[PIX(km)]);
        float2 E = make_float2(0.5f * (Yk.x + Ym.x), 0.5f * (Yk.y - Ym.y));
        float2 D = make_float2(Yk.x - Ym.x, Yk.y + Ym.y);
        float2 O = make_float2(0.5f * D.y, -0.5f * D.x);
        float2 w = g_tw[k];
        dst[k] = caddf(E, cmulf(w, O));
    }
    if (u == 0) {
        float2 Y0 = make_float2(re[PIX(0)], im[PIX(0)]);
        dst[2048] = make_float2(Y0.x - Y0.y, 0.f);
    }
}

// ---------------- conv: grid (HH, CSPLIT); partials to g_part ----------------
// Spectral stage processes an (even,odd) k-pair per lane: coalesced kf/ko loads, no parity select.
__global__ __launch_bounds__(256, 3) void k_conv() {
    extern __shared__ char smraw[];
    float*  sre = (float*)smraw;                 // 2*PADN
    float*  sim = sre + 2 * PADN;                // 2*PADN
    float2* sPD = (float2*)(sim + 2 * PADN);     // 2*2049
    int tid = threadIdx.x, s = tid >> 7, u = tid & 127;   // s = batch
    int h = blockIdx.x;
    int split = blockIdx.y;
    float* re = sre + s * PADN;
    float* im = sim + s * PADN;

    for (int b = 0; b < NBATCH; ++b) {
        const float2* pf = g_pdf + ((size_t)b * HH + h) * 2049;
        for (int m = tid; m < 2049; m += 256) sPD[b * 2049 + m] = pf[m];
    }
    float racc0[8], racc1[8];
    #pragma unroll
    for (int i = 0; i < 8; ++i) { racc0[i] = 0.f; racc1[i] = 0.f; }
    __syncthreads();

    const float2* sPDs = sPD + s * 2049;
    int cbeg = split * (CCHN / CSPLIT);
    for (int ci = 0; ci < CCHN / CSPLIT; ++ci) {
        int c = cbeg + ci;
        const float2* kf = g_kf   + ((size_t)c * HH + h) * LF;
        const float2* ko = g_kodd + ((size_t)c * HH + h) * 1024;
        #pragma unroll
        for (int m = 0; m < 8; ++m) {
            int idx = u + 128 * m;                    // 0..1023
            int ke  = 2 * idx;                        // even k: 0..2046
            // K spectrum: even bins from kf, odd bins from ko — all coalesced
            float2 KaE = kf[idx];                     // K[ke]
            float2 KaO = ko[idx];                     // K[ke+1]
            float2 KbE = kf[1024 - idx];              // K[2048-ke]
            float2 KbO = ko[1023 - idx];              // K[2047-ke] (odd)
            // even k = ke
            {
                float2 Xk = cmulf(sPDs[ke],        KaE);
                float2 X2 = cmulf(sPDs[2048 - ke], KbE);
                float2 E = make_float2(0.5f * (Xk.x + X2.x), 0.5f * (Xk.y - X2.y));
                float2 D = make_float2(Xk.x - X2.x, Xk.y + X2.y);
                float2 w = g_tw[ke];
                float2 O = make_float2(0.5f * (D.x * w.x + D.y * w.y),
                                       0.5f * (D.y * w.x - D.x * w.y));
                re[PIX(ke)] = E.x - O.y;
                im[PIX(ke)] = E.y + O.x;
            }
            // odd k = ke+1
            {
                int k1 = ke + 1;
                float2 Xk = cmulf(sPDs[k1],        KaO);
                float2 X2 = cmulf(sPDs[2048 - k1], KbO);
                float2 E = make_float2(0.5f * (Xk.x + X2.x), 0.5f * (Xk.y - X2.y));
                float2 D = make_float2(Xk.x - X2.x, Xk.y + X2.y);
                float2 w = g_tw[k1];
                float2 O = make_float2(0.5f * (D.x * w.x + D.y * w.y),
                                       0.5f * (D.y * w.x - D.x * w.y));
                re[PIX(k1)] = E.x - O.y;
                im[PIX(k1)] = E.y + O.x;
            }
        }
        fft2048<1, 0>(re, im, u);
        const float* wv = g_dCt + ((size_t)h * CCHN + c) * LL;
        #pragma unroll
        for (int i = 0; i < 8; ++i) {
            int l = tid + 256 * i;
            int pi = PIX(l >> 1);
            float wl = (1.0f / 2048.0f) * wv[l];
            float x0 = (l & 1) ? sim[pi] : sre[pi];
            float x1 = (l & 1) ? sim[PADN + pi] : sre[PADN + pi];
            racc0[i] += x0 * wl;
            racc1[i] += x1 * wl;
        }
        __syncthreads();
    }
    float* p0 = g_part + (((size_t)split * NBATCH + 0) * HH + h) * LL;
    float* p1 = g_part + (((size_t)split * NBATCH + 1) * HH + h) * LL;
    #pragma unroll
    for (int i = 0; i < 8; ++i) {
        int l = tid + 256 * i;
        p0[l] = racc0[i];
        p1[l] = racc1[i];
    }
}

// ---------------- reduce partials -> out ----------------
__global__ void k_reduce(float* __restrict__ out) {
    int i = blockIdx.x * blockDim.x + threadIdx.x;     // over NBATCH*HH*LL
    const int TOT = NBATCH * HH * LL;
    if (i >= TOT) return;
    float v = 0.f;
    #pragma unroll
    for (int sp = 0; sp < CSPLIT; ++sp)
        v += g_part[(size_t)sp * TOT + i];
    out[i] = v;
}

// ---------------- launch ----------------
extern "C" void kernel_launch(void* const* d_in, const int* in_sizes, int n_in,
                              void* d_out, int out_size) {
    const float* log_dt = (const float*)d_in[0];
    const float* B_ri   = (const float*)d_in[1];
    const float* P_ri   = (const float*)d_in[2];
    const float* C_ri   = (const float*)d_in[3];
    const float* iwr    = (const float*)d_in[4];
    const float* wim    = (const float*)d_in[5];
    const float* dC     = (const float*)d_in[6];
    const float* pd     = (const float*)d_in[7];
    float* out = (float*)d_out;
    (void)in_sizes; (void)n_in; (void)out_size;

    const int SM_CONV = (2 * PADN * 2) * (int)sizeof(float)       // sre+sim
                      + 2 * 2049 * (int)sizeof(float2);           // sPD both batches
    cudaFuncSetAttribute(k_conv, cudaFuncAttributeMaxDynamicSharedMemorySize, SM_CONV);

    k_init_tw<<<8, 256>>>();
    k_transpose<<<dim3(LL / 32, HH), 256>>>(dC);
    k_cauchy<<<dim3((LF + 127) / 128, HH, 2), 128>>>(log_dt, B_ri, P_ri, C_ri, iwr, wim);
    k_kernelfft<<<CCHN * HH / 4, 256>>>();
    k_pdfft<<<NBATCH * HH / 2, 256>>>(pd);
    k_conv<<<dim3(HH, CSPLIT), 256, SM_CONV>>>();
    k_reduce<<<(NBATCH * HH * LL + 255) / 256, 256>>>(out);
}

// round 14
// speedup vs baseline: 1.2173x; 1.0386x over previous
#include <cuda_runtime.h>
#include <math.h>

#define HH 256
#define NN 32
#define CCHN 32
#define LL 2048
#define LF 1025
#define NBATCH 2
#define CSPLIT 8
#define PADN 2176                       // 2048 + 128 pad floats
#define PIX(a) ((a) + ((a) >> 4))

// ---------------- scratch ----------------
__device__ float2 g_tw[2048];                 // e^{-2*pi*i*k/4096}
__device__ float2 g_kf  [CCHN * HH * LF];     // (C,H,1025) 2048-DFT of kernel (= even bins of 4096-DFT)
__device__ float2 g_kodd[CCHN * HH * 1024];   // odd bins of 4096-DFT
__device__ float2 g_pdf [NBATCH * HH * 2049]; // rfft(pd, 4096)
__device__ float  g_dCt [HH * CCHN * LL];     // (H,C,L)
__device__ float  g_part[CSPLIT * NBATCH * HH * LL]; // conv partial sums (33.6 MB)

__device__ __forceinline__ float2 cmulf(float2 a, float2 b) {
    return make_float2(a.x * b.x - a.y * b.y, a.x * b.y + a.y * b.x);
}
__device__ __forceinline__ float2 caddf(float2 a, float2 b) { return make_float2(a.x + b.x, a.y + b.y); }
__device__ __forceinline__ float2 csubf(float2 a, float2 b) { return make_float2(a.x - b.x, a.y - b.y); }

// ---- packed f32x2 helpers (sm_103a FFMA2 path, PTX-only) ----
__device__ __forceinline__ unsigned long long fma2(unsigned long long a, unsigned long long b,
                                                   unsigned long long c) {
    unsigned long long d;
    asm("fma.rn.f32x2 %0, %1, %2, %3;" : "=l"(d) : "l"(a), "l"(b), "l"(c));
    return d;
}
__device__ __forceinline__ unsigned long long pack2(float lo, float hi) {
    unsigned long long r;
    asm("mov.b64 %0, {%1, %2};" : "=l"(r) : "f"(lo), "f"(hi));
    return r;
}
__device__ __forceinline__ void unpack2(unsigned long long v, float& lo, float& hi) {
    asm("mov.b64 {%0, %1}, %2;" : "=f"(lo), "=f"(hi) : "l"(v));
}

__global__ void k_init_tw() {
    int i = blockIdx.x * blockDim.x + threadIdx.x;
    if (i < 2048) {
        double a = -M_PI * (double)i / 2048.0;
        g_tw[i] = make_float2((float)cos(a), (float)sin(a));
    }
}

// ---------------- dC transpose: (L,H,C) -> (H,C,L) ----------------
__global__ void k_transpose(const float* __restrict__ dC) {
    __shared__ float t[32][33];
    int h  = blockIdx.y;
    int l0 = blockIdx.x * 32;
    int tid = threadIdx.x;
    int c = tid & 31, r = tid >> 5;
    for (int i = r; i < 32; i += 8)
        t[i][c] = dC[(size_t)(l0 + i) * (HH * NN) + h * NN + c];
    __syncthreads();
    int li = tid & 31, cc = tid >> 5;
    for (int i = cc; i < 32; i += 8)
        g_dCt[((size_t)h * CCHN + i) * LL + l0 + li] = t[li][i];
}

// ---------------- small DFTs in registers ----------------
__device__ __forceinline__ void dft4(float2& a, float2& b, float2& c, float2& d, int inv) {
    float2 A = caddf(a, c), B = csubf(a, c), C = caddf(b, d), D = csubf(b, d);
    a = caddf(A, C); c = csubf(A, C);
    if (!inv) { b = make_float2(B.x + D.y, B.y - D.x); d = make_float2(B.x - D.y, B.y + D.x); }
    else      { b = make_float2(B.x - D.y, B.y + D.x); d = make_float2(B.x + D.y, B.y - D.x); }
}

__device__ __forceinline__ void dft8(float2 x[8], int inv) {
    float2 e0 = x[0], e1 = x[2], e2 = x[4], e3 = x[6];
    float2 o0 = x[1], o1 = x[3], o2 = x[5], o3 = x[7];
    dft4(e0, e1, e2, e3, inv);
    dft4(o0, o1, o2, o3, inv);
    const float r = 0.70710678118654752f;
    float sg = inv ? 1.f : -1.f;
    float2 w1 = make_float2(r, sg * r);
    float2 w2 = make_float2(0.f, sg);
    float2 w3 = make_float2(-r, sg * r);
    o1 = cmulf(o1, w1); o2 = cmulf(o2, w2); o3 = cmulf(o3, w3);
    x[0] = caddf(e0, o0); x[4] = csubf(e0, o0);
    x[1] = caddf(e1, o1); x[5] = csubf(e1, o1);
    x[2] = caddf(e2, o2); x[6] = csubf(e2, o2);
    x[3] = caddf(e3, o3); x[7] = csubf(e3, o3);
}

// 16-pt DFT; output X[k1+4k2] lands at x[4*k1+k2] (use perm on store)
__device__ __forceinline__ void dft16(float2 x[16], int inv) {
    #pragma unroll
    for (int n1 = 0; n1 < 4; ++n1)
        dft4(x[n1], x[n1 + 4], x[n1 + 8], x[n1 + 12], inv);
    const float c1 = 0.92387953251128675f, s1 = 0.38268343236508977f, r = 0.70710678118654752f;
    float sg = inv ? 1.f : -1.f;
    float2 W1 = make_float2(c1,  sg * s1);
    float2 W2 = make_float2(r,   sg * r);
    float2 W3 = make_float2(s1,  sg * c1);
    float2 W4 = make_float2(0.f, sg);
    float2 W6 = make_float2(-r,  sg * r);
    float2 W9 = make_float2(-c1, -sg * s1);
    x[5]  = cmulf(x[5],  W1);
    x[9]  = cmulf(x[9],  W2);
    x[13] = cmulf(x[13], W3);
    x[6]  = cmulf(x[6],  W2);
    x[10] = cmulf(x[10], W4);
    x[14] = cmulf(x[14], W6);
    x[7]  = cmulf(x[7],  W3);
    x[11] = cmulf(x[11], W6);
    x[15] = cmulf(x[15], W9);
    #pragma unroll
    for (int k1 = 0; k1 < 4; ++k1)
        dft4(x[4 * k1], x[4 * k1 + 1], x[4 * k1 + 2], x[4 * k1 + 3], inv);
}

// ---------------- 2048-pt FFT, 128 threads per sub-FFT, radix 16/16/8 ----------------
// PREMOD: stage-0 load multiplies by scale*g_tw[a] (fuses the modulate pass).
template <int INV, int PREMOD>
__device__ void fft2048(float* re, float* im, int u, float scale = 1.0f) {
    float2 x[16];
    __syncthreads();
    #pragma unroll
    for (int m = 0; m < 16; ++m) {
        int a = u + 128 * m, i = PIX(a);
        float2 v = make_float2(re[i], im[i]);
        if (PREMOD) {
            float2 w = g_tw[a];
            v = make_float2(scale * (v.x * w.x - v.y * w.y),
                            scale * (v.x * w.y + v.y * w.x));
        }
        x[m] = v;
    }
    dft16(x, INV);
    __syncthreads();
    #pragma unroll
    for (int m = 0; m < 16; ++m) {
        int d = 16 * u + m, i = PIX(d);
        float2 v = x[((m & 3) << 2) | (m >> 2)];
        re[i] = v.x; im[i] = v.y;
    }
    __syncthreads();
    #pragma unroll
    for (int m = 0; m < 16; ++m) { int a = u + 128 * m, i = PIX(a); x[m] = make_float2(re[i], im[i]); }
    {
        int p = u & 15;
        float2 w = g_tw[16 * p];
        if (INV) w.y = -w.y;
        float2 cur = w;
        #pragma unroll
        for (int m = 1; m < 16; ++m) { x[m] = cmulf(x[m], cur); cur = cmulf(cur, w); }
    }
    dft16(x, INV);
    __syncthreads();
    {
        int base = ((u >> 4) << 8) + (u & 15);
        #pragma unroll
        for (int m = 0; m < 16; ++m) {
            int d = base + 16 * m, i = PIX(d);
            float2 v = x[((m & 3) << 2) | (m >> 2)];
            re[i] = v.x; im[i] = v.y;
        }
    }
    __syncthreads();
    float2 e[8], f[8];
    #pragma unroll
    for (int m = 0; m < 8; ++m) {
        int a0 = u + 256 * m, a1 = u + 128 + 256 * m;
        e[m] = make_float2(re[PIX(a0)], im[PIX(a0)]);
        f[m] = make_float2(re[PIX(a1)], im[PIX(a1)]);
    }
    {
        float2 w0 = g_tw[2 * u], w1 = g_tw[2 * (u + 128)];
        if (INV) { w0.y = -w0.y; w1.y = -w1.y; }
        float2 c0 = w0, c1 = w1;
        #pragma unroll
        for (int m = 1; m < 8; ++m) {
            e[m] = cmulf(e[m], c0); c0 = cmulf(c0, w0);
            f[m] = cmulf(f[m], c1); c1 = cmulf(c1, w1);
        }
    }
    dft8(e, INV); dft8(f, INV);
    __syncthreads();
    #pragma unroll
    for (int m = 0; m < 8; ++m) {
        int d0 = u + 256 * m, d1 = u + 128 + 256 * m;
        re[PIX(d0)] = e[m].x; im[PIX(d0)] = e[m].y;
        re[PIX(d1)] = f[m].x; im[PIX(d1)] = f[m].y;
    }
    __syncthreads();
}

// ---------------- Cauchy + Woodbury -> k_f (C,H,1025) ----------------
// Conjugate-pair collapse: term = g*alpha + e*beta, alpha=2(z-wr)/D, beta=-2wi/D,
// D = z^2 - 2wr z + |w|^2; g=Re(B*C), e=Im(B*C) precomputed per block (l-invariant).
__global__ __launch_bounds__(128, 4) void k_cauchy(
    const float* __restrict__ log_dt, const float* __restrict__ B_ri,
    const float* __restrict__ P_ri,   const float* __restrict__ C_ri,
    const float* __restrict__ iwr,    const float* __restrict__ wim) {
    int h    = blockIdx.y;
    int half = blockIdx.z;
    int c0   = half * 16;
    int tid  = threadIdx.x;
    int l    = blockIdx.x * blockDim.x + tid;

    __shared__ float4 sW4[NN];        // (wr, wi, |w|^2, 0)
    __shared__ float4 sQ[NN];         // (gq0, eq0, gq1, 0)
    __shared__ float4 sT1[16][NN];    // (g0, g0, e0, e0)  B-row
    __shared__ float4 sT2[16][NN];    // (g1, g1, e1, e1)  P-row

    float dt = expf(log_dt[h]);
    if (tid < NN) {
        float2 B = ((const float2*)B_ri)[h * NN + tid];
        float2 P = ((const float2*)P_ri)[h * NN + tid];
        float wr = -expf(iwr[h * NN + tid]) * dt;
        float wi = wim[h * NN + tid] * dt;
        sW4[tid] = make_float4(wr, wi, wr * wr + wi * wi, 0.f);
        // Q-row channel Cq = conj(P):  v0 = B*conj(P),  v1 = P*conj(P) = |P|^2
        sQ[tid] = make_float4(B.x * P.x + B.y * P.y,
                              B.y * P.x - B.x * P.y,
                              P.x * P.x + P.y * P.y, 0.f);
    }
    for (int i = tid; i < 16 * NN; i += blockDim.x) {
        int j = i / NN, n = i % NN;
        float2 C = ((const float2*)C_ri)[(c0 + j) * (HH * NN) + h * NN + n];
        float2 B = ((const float2*)B_ri)[h * NN + n];
        float2 P = ((const float2*)P_ri)[h * NN + n];
        float g0 = B.x * C.x - B.y * C.y, e0 = B.x * C.y + B.y * C.x;
        float g1 = P.x * C.x - P.y * C.y, e1 = P.x * C.y + P.y * C.x;
        sT1[j][n] = make_float4(g0, g0, e0, e0);
        sT2[j][n] = make_float4(g1, g1, e1, e1);
    }
    __syncthreads();

    if (l >= LF) return;

    if (l == LL / 2) {
        // analytic Nyquist limit: k_f[c] = dt * Re(sum_n B[n]*C[c][n]) = dt * sum_n g0
        #pragma unroll
        for (int j = 0; j < 16; ++j) {
            float acc = 0.f;
            #pragma unroll
            for (int n = 0; n < NN; ++n)
                acc += sT1[j][n].x;
            g_kf[((c0 + j) * HH + h) * LF + l] = make_float2(dt * acc, 0.f);
        }
        return;
    }

    float s, cg;
    sincospif((float)l * (1.0f / 1024.0f), &s, &cg);
    float2 om  = make_float2(cg, -s);
    float2 den = make_float2(1.f + om.x, om.y);
    float  dn  = den.x * den.x + den.y * den.y;
    float2 num = make_float2(1.f - om.x, -om.y);
    float zx = 2.f * (num.x * den.x + num.y * den.y) / dn;
    float zy = 2.f * (num.y * den.x - num.x * den.y) / dn;
    float2 fac = make_float2(2.f * den.x / dn, -2.f * den.y / dn);
    float z2x = zx * zx - zy * zy;
    float z2y = 2.f * zx * zy;

    unsigned long long A0[16], A1[16];
    unsigned long long A0q = 0ULL, A1q = 0ULL;
    #pragma unroll
    for (int j = 0; j < 16; ++j) { A0[j] = 0ULL; A1[j] = 0ULL; }

    #pragma unroll
    for (int n = 0; n < NN; ++n) {
        float4 W = sW4[n];
        float Dx = z2x + W.z - 2.f * W.x * zx;
        float Dy = z2y - 2.f * W.x * zy;
        float ir = 1.f / (Dx * Dx + Dy * Dy);
        float ivx = Dx * ir, ivy = -Dy * ir;          // 1/D
        float ax = zx - W.x;                          // z - wr
        float alr = 2.f * (ax * ivx - zy * ivy);
        float ali = 2.f * (ax * ivy + zy * ivx);
        float ber = -2.f * W.y * ivx;
        float bei = -2.f * W.y * ivy;
        unsigned long long ALPHA = pack2(alr, ali);
        unsigned long long BETA  = pack2(ber, bei);
        #pragma unroll
        for (int j = 0; j < 16; ++j) {
            union { float4 f; unsigned long long u64[2]; } c1, c2;
            c1.f = sT1[j][n];
            c2.f = sT2[j][n];
            A0[j] = fma2(c1.u64[0], ALPHA, A0[j]);
            A0[j] = fma2(c1.u64[1], BETA,  A0[j]);
            A1[j] = fma2(c2.u64[0], ALPHA, A1[j]);
            A1[j] = fma2(c2.u64[1], BETA,  A1[j]);
        }
        float4 q = sQ[n];
        A0q = fma2(pack2(q.x, q.x), ALPHA, A0q);
        A0q = fma2(pack2(q.y, q.y), BETA,  A0q);
        A1q = fma2(pack2(q.z, q.z), ALPHA, A1q);      // e=0 for |P|^2 row
    }

    float2 r0q, r1q;
    unpack2(A0q, r0q.x, r0q.y);
    unpack2(A1q, r1q.x, r1q.y);
    r0q.x *= dt; r0q.y *= dt; r1q.x *= dt; r1q.y *= dt;
    float2 onep = make_float2(1.f + r1q.x, r1q.y);
    float  oin  = 1.f / (onep.x * onep.x + onep.y * onep.y);
    float2 coef = cmulf(r0q, make_float2(onep.x * oin, -onep.y * oin)); // r0q/(1+r1q)

    #pragma unroll
    for (int j = 0; j < 16; ++j) {
        float2 a0j, a1j;
        unpack2(A0[j], a0j.x, a0j.y);
        unpack2(A1[j], a1j.x, a1j.y);
        float2 R0 = make_float2(a0j.x * dt, a0j.y * dt);
        float2 R1 = make_float2(a1j.x * dt, a1j.y * dt);
        float2 corr = cmulf(coef, R1);
        float2 kf = cmulf(csubf(R0, corr), fac);
        g_kf[((c0 + j) * HH + h) * LF + l] = kf;
    }
}

// ---------------- odd bins of the 4096-DFT of the kernel ----------------
// 2-channel complex packing + premod-fused second FFT. (R11-proven)
__global__ __launch_bounds__(256, 3) void k_kernelfft() {
    __shared__ float sre[2 * PADN], sim[2 * PADN];
    int s = threadIdx.x >> 7, u = threadIdx.x & 127;
    int p = blockIdx.x * 2 + s;                       // pair index in [0, 4096)
    int c1 = (p >> 8) * 2;                            // even channel
    int h  = p & 255;
    int ch1 = c1 * HH + h;
    int ch2 = ch1 + HH;                               // channel c1+1, same h
    float* re = sre + s * PADN;
    float* im = sim + s * PADN;

    const float2* kf1 = g_kf + (size_t)ch1 * LF;
    const float2* kf2 = g_kf + (size_t)ch2 * LF;
    for (int i = u; i <= 1024; i += 128) {
        float2 X1 = kf1[i];
        float2 X2 = kf2[i];
        re[PIX(i)] = X1.x - X2.y;                     // Z = X1 + i*X2
        im[PIX(i)] = X1.y + X2.x;
        if (i >= 1 && i < 1024) {
            int m = 2048 - i;                         // conj(X1) + i*conj(X2)
            re[PIX(m)] = X1.x + X2.y;
            im[PIX(m)] = X2.x - X1.y;
        }
    }
    fft2048<1, 0>(re, im, u);                         // z = (k1 + i*k2) * 2048
    fft2048<0, 1>(re, im, u, 1.0f / 2048.0f);         // Y = FFT(z/2048 * e^{-i*pi*l/2048})
    float2* d1 = g_kodd + (size_t)ch1 * 1024;
    float2* d2 = g_kodd + (size_t)ch2 * 1024;
    for (int j = u; j < 1024; j += 128) {
        int pj = PIX(j), pm = PIX(2047 - j);
        float Pr = re[pj], Pi = im[pj];
        float Mr = re[pm], Mi = im[pm];
        d1[j] = make_float2(0.5f * (Pr + Mr), 0.5f * (Pi - Mi));
        d2[j] = make_float2(0.5f * (Pi + Mi), 0.5f * (Mr - Pr));
    }
}

// ---------------- rfft(pd, 4096) via real packing (2 rows/block) ----------------
__global__ __launch_bounds__(256, 3) void k_pdfft(const float* __restrict__ pd) {
    __shared__ float sre[2 * PADN], sim[2 * PADN];
    int s = threadIdx.x >> 7, u = threadIdx.x & 127;
    int ch = blockIdx.x * 2 + s;                      // b*256 + h
    float* re = sre + s * PADN;
    float* im = sim + s * PADN;

    const float* src = pd + (size_t)ch * LL;
    for (int n = u; n < 2048; n += 128) {
        if (n < 1024) { re[PIX(n)] = src[2 * n]; im[PIX(n)] = src[2 * n + 1]; }
        else          { re[PIX(n)] = 0.f;        im[PIX(n)] = 0.f; }
    }
    fft2048<0, 0>(re, im, u);
    float2* dst = g_pdf + (size_t)ch * 2049;
    for (int k = u; k < 2048; k += 128) {
        float2 Yk = make_float2(re[PIX(k)], im[PIX(k)]);
        int km = (2048 - k) & 2047;
        float2 Ym = make_float2(re[PIX(km)], im[PIX(km)]);
        float2 E = make_float2(0.5f * (Yk.x + Ym.x), 0.5f * (Yk.y - Ym.y));
        float2 D = make_float2(Yk.x - Ym.x, Yk.y + Ym.y);
        float2 O = make_float2(0.5f * D.y, -0.5f * D.x);
        float2 w = g_tw[k];
        dst[k] = caddf(E, cmulf(w, O));
    }
    if (u == 0) {
        float2 Y0 = make_float2(re[PIX(0)], im[PIX(0)]);
        dst[2048] = make_float2(Y0.x - Y0.y, 0.f);
    }
}

// ---------------- conv: grid (HH, CSPLIT); partials to g_part ----------------
// Spectral stage processes an (even,odd) k-pair per lane: coalesced kf/ko loads, no parity select.
__global__ __launch_bounds__(256, 3) void k_conv() {
    extern __shared__ char smraw[];
    float*  sre = (float*)smraw;                 // 2*PADN
    float*  sim = sre + 2 * PADN;                // 2*PADN
    float2* sPD = (float2*)(sim + 2 * PADN);     // 2*2049
    int tid = threadIdx.x, s = tid >> 7, u = tid & 127;   // s = batch
    int h = blockIdx.x;
    int split = blockIdx.y;
    float* re = sre + s * PADN;
    float* im = sim + s * PADN;

    for (int b = 0; b < NBATCH; ++b) {
        const float2* pf = g_pdf + ((size_t)b * HH + h) * 2049;
        for (int m = tid; m < 2049; m += 256) sPD[b * 2049 + m] = pf[m];
    }
    float racc0[8], racc1[8];
    #pragma unroll
    for (int i = 0; i < 8; ++i) { racc0[i] = 0.f; racc1[i] = 0.f; }
    __syncthreads();

    const float2* sPDs = sPD + s * 2049;
    int cbeg = split * (CCHN / CSPLIT);
    for (int ci = 0; ci < CCHN / CSPLIT; ++ci) {
        int c = cbeg + ci;
        const float2* kf = g_kf   + ((size_t)c * HH + h) * LF;
        const float2* ko = g_kodd + ((size_t)c * HH + h) * 1024;
        #pragma unroll
        for (int m = 0; m < 8; ++m) {
            int idx = u + 128 * m;                    // 0..1023
            int ke  = 2 * idx;                        // even k: 0..2046
            float2 KaE = kf[idx];                     // K[ke]
            float2 KaO = ko[idx];                     // K[ke+1]
            float2 KbE = kf[1024 - idx];              // K[2048-ke]
            float2 KbO = ko[1023 - idx];              // K[2047-ke] (odd)
            {
                float2 Xk = cmulf(sPDs[ke],        KaE);
                float2 X2 = cmulf(sPDs[2048 - ke], KbE);
                float2 E = make_float2(0.5f * (Xk.x + X2.x), 0.5f * (Xk.y - X2.y));
                float2 D = make_float2(Xk.x - X2.x, Xk.y + X2.y);
                float2 w = g_tw[ke];
                float2 O = make_float2(0.5f * (D.x * w.x + D.y * w.y),
                                       0.5f * (D.y * w.x - D.x * w.y));
                re[PIX(ke)] = E.x - O.y;
                im[PIX(ke)] = E.y + O.x;
            }
            {
                int k1 = ke + 1;
                float2 Xk = cmulf(sPDs[k1],        KaO);
                float2 X2 = cmulf(sPDs[2048 - k1], KbO);
                float2 E = make_float2(0.5f * (Xk.x + X2.x), 0.5f * (Xk.y - X2.y));
                float2 D = make_float2(Xk.x - X2.x, Xk.y + X2.y);
                float2 w = g_tw[k1];
                float2 O = make_float2(0.5f * (D.x * w.x + D.y * w.y),
                                       0.5f * (D.y * w.x - D.x * w.y));
                re[PIX(k1)] = E.x - O.y;
                im[PIX(k1)] = E.y + O.x;
            }
        }
        fft2048<1, 0>(re, im, u);
        const float* wv = g_dCt + ((size_t)h * CCHN + c) * LL;
        #pragma unroll
        for (int i = 0; i < 8; ++i) {
            int l = tid + 256 * i;
            int pi = PIX(l >> 1);
            float wl = (1.0f / 2048.0f) * wv[l];
            float x0 = (l & 1) ? sim[pi] : sre[pi];
            float x1 = (l & 1) ? sim[PADN + pi] : sre[PADN + pi];
            racc0[i] += x0 * wl;
            racc1[i] += x1 * wl;
        }
        __syncthreads();
    }
    float* p0 = g_part + (((size_t)split * NBATCH + 0) * HH + h) * LL;
    float* p1 = g_part + (((size_t)split * NBATCH + 1) * HH + h) * LL;
    #pragma unroll
    for (int i = 0; i < 8; ++i) {
        int l = tid + 256 * i;
        p0[l] = racc0[i];
        p1[l] = racc1[i];
    }
}

// ---------------- reduce partials -> out ----------------
__global__ void k_reduce(float* __restrict__ out) {
    int i = blockIdx.x * blockDim.x + threadIdx.x;     // over NBATCH*HH*LL
    const int TOT = NBATCH * HH * LL;
    if (i >= TOT) return;
    float v = 0.f;
    #pragma unroll
    for (int sp = 0; sp < CSPLIT; ++sp)
        v += g_part[(size_t)sp * TOT + i];
    out[i] = v;
}

// ---------------- launch ----------------
extern "C" void kernel_launch(void* const* d_in, const int* in_sizes, int n_in,
                              void* d_out, int out_size) {
    const float* log_dt = (const float*)d_in[0];
    const float* B_ri   = (const float*)d_in[1];
    const float* P_ri   = (const float*)d_in[2];
    const float* C_ri   = (const float*)d_in[3];
    const float* iwr    = (const float*)d_in[4];
    const float* wim    = (const float*)d_in[5];
    const float* dC     = (const float*)d_in[6];
    const float* pd     = (const float*)d_in[7];
    float* out = (float*)d_out;
    (void)in_sizes; (void)n_in; (void)out_size;

    const int SM_CONV = (2 * PADN * 2) * (int)sizeof(float)       // sre+sim
                      + 2 * 2049 * (int)sizeof(float2);           // sPD both batches
    cudaFuncSetAttribute(k_conv, cudaFuncAttributeMaxDynamicSharedMemorySize, SM_CONV);

    k_init_tw<<<8, 256>>>();
    k_transpose<<<dim3(LL / 32, HH), 256>>>(dC);
    k_cauchy<<<dim3((LF + 127) / 128, HH, 2), 128>>>(log_dt, B_ri, P_ri, C_ri, iwr, wim);
    k_kernelfft<<<CCHN * HH / 4, 256>>>();
    k_pdfft<<<NBATCH * HH / 2, 256>>>(pd);
    k_conv<<<dim3(HH, CSPLIT), 256, SM_CONV>>>();
    k_reduce<<<(NBATCH * HH * LL + 255) / 256, 256>>>(out);
}

// round 15
// speedup vs baseline: 1.2614x; 1.0362x over previous
#include <cuda_runtime.h>
#include <math.h>

#define HH 256
#define NN 32
#define CCHN 32
#define LL 2048
#define LF 1025
#define NBATCH 2
#define CSPLIT 8
#define PADN 2176                       // 2048 + 128 pad floats
#define PIX(a) ((a) + ((a) >> 4))

// ---------------- scratch ----------------
__device__ float2 g_tw[2048];                 // e^{-2*pi*i*k/4096}
__device__ float2 g_kf  [CCHN * HH * LF];     // (C,H,1025) 2048-DFT of kernel (= even bins of 4096-DFT)
__device__ float2 g_kodd[CCHN * HH * 1024];   // odd bins of 4096-DFT
__device__ float2 g_pdf [NBATCH * HH * 2049]; // rfft(pd, 4096)
__device__ float  g_dCt [HH * CCHN * LL];     // (H,C,L)
__device__ float  g_part[CSPLIT * NBATCH * HH * LL]; // conv partial sums (33.6 MB)

__device__ __forceinline__ float2 cmulf(float2 a, float2 b) {
    return make_float2(a.x * b.x - a.y * b.y, a.x * b.y + a.y * b.x);
}
__device__ __forceinline__ float2 caddf(float2 a, float2 b) { return make_float2(a.x + b.x, a.y + b.y); }
__device__ __forceinline__ float2 csubf(float2 a, float2 b) { return make_float2(a.x - b.x, a.y - b.y); }

// ---- packed f32x2 helpers (sm_103a FFMA2 path, PTX-only) ----
__device__ __forceinline__ unsigned long long fma2(unsigned long long a, unsigned long long b,
                                                   unsigned long long c) {
    unsigned long long d;
    asm("fma.rn.f32x2 %0, %1, %2, %3;" : "=l"(d) : "l"(a), "l"(b), "l"(c));
    return d;
}
__device__ __forceinline__ unsigned long long pack2(float lo, float hi) {
    unsigned long long r;
    asm("mov.b64 %0, {%1, %2};" : "=l"(r) : "f"(lo), "f"(hi));
    return r;
}
__device__ __forceinline__ void unpack2(unsigned long long v, float& lo, float& hi) {
    asm("mov.b64 {%0, %1}, %2;" : "=f"(lo), "=f"(hi) : "l"(v));
}

__global__ void k_init_tw() {
    int i = blockIdx.x * blockDim.x + threadIdx.x;
    if (i < 2048) {
        double a = -M_PI * (double)i / 2048.0;
        g_tw[i] = make_float2((float)cos(a), (float)sin(a));
    }
}

// ---------------- dC transpose: (L,H,C) -> (H,C,L) ----------------
__global__ void k_transpose(const float* __restrict__ dC) {
    __shared__ float t[32][33];
    int h  = blockIdx.y;
    int l0 = blockIdx.x * 32;
    int tid = threadIdx.x;
    int c = tid & 31, r = tid >> 5;
    for (int i = r; i < 32; i += 8)
        t[i][c] = dC[(size_t)(l0 + i) * (HH * NN) + h * NN + c];
    __syncthreads();
    int li = tid & 31, cc = tid >> 5;
    for (int i = cc; i < 32; i += 8)
        g_dCt[((size_t)h * CCHN + i) * LL + l0 + li] = t[li][i];
}

// ---------------- small DFTs in registers ----------------
__device__ __forceinline__ void dft4(float2& a, float2& b, float2& c, float2& d, int inv) {
    float2 A = caddf(a, c), B = csubf(a, c), C = caddf(b, d), D = csubf(b, d);
    a = caddf(A, C); c = csubf(A, C);
    if (!inv) { b = make_float2(B.x + D.y, B.y - D.x); d = make_float2(B.x - D.y, B.y + D.x); }
    else      { b = make_float2(B.x - D.y, B.y + D.x); d = make_float2(B.x + D.y, B.y - D.x); }
}

__device__ __forceinline__ void dft8(float2 x[8], int inv) {
    float2 e0 = x[0], e1 = x[2], e2 = x[4], e3 = x[6];
    float2 o0 = x[1], o1 = x[3], o2 = x[5], o3 = x[7];
    dft4(e0, e1, e2, e3, inv);
    dft4(o0, o1, o2, o3, inv);
    const float r = 0.70710678118654752f;
    float sg = inv ? 1.f : -1.f;
    float2 w1 = make_float2(r, sg * r);
    float2 w2 = make_float2(0.f, sg);
    float2 w3 = make_float2(-r, sg * r);
    o1 = cmulf(o1, w1); o2 = cmulf(o2, w2); o3 = cmulf(o3, w3);
    x[0] = caddf(e0, o0); x[4] = csubf(e0, o0);
    x[1] = caddf(e1, o1); x[5] = csubf(e1, o1);
    x[2] = caddf(e2, o2); x[6] = csubf(e2, o2);
    x[3] = caddf(e3, o3); x[7] = csubf(e3, o3);
}

// 16-pt DFT; output X[k1+4k2] lands at x[4*k1+k2] (use perm on store)
__device__ __forceinline__ void dft16(float2 x[16], int inv) {
    #pragma unroll
    for (int n1 = 0; n1 < 4; ++n1)
        dft4(x[n1], x[n1 + 4], x[n1 + 8], x[n1 + 12], inv);
    const float c1 = 0.92387953251128675f, s1 = 0.38268343236508977f, r = 0.70710678118654752f;
    float sg = inv ? 1.f : -1.f;
    float2 W1 = make_float2(c1,  sg * s1);
    float2 W2 = make_float2(r,   sg * r);
    float2 W3 = make_float2(s1,  sg * c1);
    float2 W4 = make_float2(0.f, sg);
    float2 W6 = make_float2(-r,  sg * r);
    float2 W9 = make_float2(-c1, -sg * s1);
    x[5]  = cmulf(x[5],  W1);
    x[9]  = cmulf(x[9],  W2);
    x[13] = cmulf(x[13], W3);
    x[6]  = cmulf(x[6],  W2);
    x[10] = cmulf(x[10], W4);
    x[14] = cmulf(x[14], W6);
    x[7]  = cmulf(x[7],  W3);
    x[11] = cmulf(x[11], W6);
    x[15] = cmulf(x[15], W9);
    #pragma unroll
    for (int k1 = 0; k1 < 4; ++k1)
        dft4(x[4 * k1], x[4 * k1 + 1], x[4 * k1 + 2], x[4 * k1 + 3], inv);
}

// ---------------- 2048-pt FFT, 128 threads per sub-FFT, radix 16/16/8 ----------------
// PREMOD: stage-0 load multiplies by scale*g_tw[a] (fuses the modulate pass).
template <int INV, int PREMOD>
__device__ void fft2048(float* re, float* im, int u, float scale = 1.0f) {
    float2 x[16];
    __syncthreads();
    #pragma unroll
    for (int m = 0; m < 16; ++m) {
        int a = u + 128 * m, i = PIX(a);
        float2 v = make_float2(re[i], im[i]);
        if (PREMOD) {
            float2 w = g_tw[a];
            v = make_float2(scale * (v.x * w.x - v.y * w.y),
                            scale * (v.x * w.y + v.y * w.x));
        }
        x[m] = v;
    }
    dft16(x, INV);
    __syncthreads();
    #pragma unroll
    for (int m = 0; m < 16; ++m) {
        int d = 16 * u + m, i = PIX(d);
        float2 v = x[((m & 3) << 2) | (m >> 2)];
        re[i] = v.x; im[i] = v.y;
    }
    __syncthreads();
    #pragma unroll
    for (int m = 0; m < 16; ++m) { int a = u + 128 * m, i = PIX(a); x[m] = make_float2(re[i], im[i]); }
    {
        int p = u & 15;
        float2 w = g_tw[16 * p];
        if (INV) w.y = -w.y;
        float2 cur = w;
        #pragma unroll
        for (int m = 1; m < 16; ++m) { x[m] = cmulf(x[m], cur); cur = cmulf(cur, w); }
    }
    dft16(x, INV);
    __syncthreads();
    {
        int base = ((u >> 4) << 8) + (u & 15);
        #pragma unroll
        for (int m = 0; m < 16; ++m) {
            int d = base + 16 * m, i = PIX(d);
            float2 v = x[((m & 3) << 2) | (m >> 2)];
            re[i] = v.x; im[i] = v.y;
        }
    }
    __syncthreads();
    float2 e[8], f[8];
    #pragma unroll
    for (int m = 0; m < 8; ++m) {
        int a0 = u + 256 * m, a1 = u + 128 + 256 * m;
        e[m] = make_float2(re[PIX(a0)], im[PIX(a0)]);
        f[m] = make_float2(re[PIX(a1)], im[PIX(a1)]);
    }
    {
        float2 w0 = g_tw[2 * u], w1 = g_tw[2 * (u + 128)];
        if (INV) { w0.y = -w0.y; w1.y = -w1.y; }
        float2 c0 = w0, c1 = w1;
        #pragma unroll
        for (int m = 1; m < 8; ++m) {
            e[m] = cmulf(e[m], c0); c0 = cmulf(c0, w0);
            f[m] = cmulf(f[m], c1); c1 = cmulf(c1, w1);
        }
    }
    dft8(e, INV); dft8(f, INV);
    __syncthreads();
    #pragma unroll
    for (int m = 0; m < 8; ++m) {
        int d0 = u + 256 * m, d1 = u + 128 + 256 * m;
        re[PIX(d0)] = e[m].x; im[PIX(d0)] = e[m].y;
        re[PIX(d1)] = f[m].x; im[PIX(d1)] = f[m].y;
    }
    __syncthreads();
}

// ---------------- Cauchy + Woodbury -> k_f (C,H,1025) ----------------
// Conjugate-pair collapse (R14-proven).
__global__ __launch_bounds__(128, 4) void k_cauchy(
    const float* __restrict__ log_dt, const float* __restrict__ B_ri,
    const float* __restrict__ P_ri,   const float* __restrict__ C_ri,
    const float* __restrict__ iwr,    const float* __restrict__ wim) {
    int h    = blockIdx.y;
    int half = blockIdx.z;
    int c0   = half * 16;
    int tid  = threadIdx.x;
    int l    = blockIdx.x * blockDim.x + tid;

    __shared__ float4 sW4[NN];        // (wr, wi, |w|^2, 0)
    __shared__ float4 sQ[NN];         // (gq0, eq0, gq1, 0)
    __shared__ float4 sT1[16][NN];    // (g0, g0, e0, e0)  B-row
    __shared__ float4 sT2[16][NN];    // (g1, g1, e1, e1)  P-row

    float dt = expf(log_dt[h]);
    if (tid < NN) {
        float2 B = ((const float2*)B_ri)[h * NN + tid];
        float2 P = ((const float2*)P_ri)[h * NN + tid];
        float wr = -expf(iwr[h * NN + tid]) * dt;
        float wi = wim[h * NN + tid] * dt;
        sW4[tid] = make_float4(wr, wi, wr * wr + wi * wi, 0.f);
        sQ[tid] = make_float4(B.x * P.x + B.y * P.y,
                              B.y * P.x - B.x * P.y,
                              P.x * P.x + P.y * P.y, 0.f);
    }
    for (int i = tid; i < 16 * NN; i += blockDim.x) {
        int j = i / NN, n = i % NN;
        float2 C = ((const float2*)C_ri)[(c0 + j) * (HH * NN) + h * NN + n];
        float2 B = ((const float2*)B_ri)[h * NN + n];
        float2 P = ((const float2*)P_ri)[h * NN + n];
        float g0 = B.x * C.x - B.y * C.y, e0 = B.x * C.y + B.y * C.x;
        float g1 = P.x * C.x - P.y * C.y, e1 = P.x * C.y + P.y * C.x;
        sT1[j][n] = make_float4(g0, g0, e0, e0);
        sT2[j][n] = make_float4(g1, g1, e1, e1);
    }
    __syncthreads();

    if (l >= LF) return;

    if (l == LL / 2) {
        #pragma unroll
        for (int j = 0; j < 16; ++j) {
            float acc = 0.f;
            #pragma unroll
            for (int n = 0; n < NN; ++n)
                acc += sT1[j][n].x;
            g_kf[((c0 + j) * HH + h) * LF + l] = make_float2(dt * acc, 0.f);
        }
        return;
    }

    float s, cg;
    sincospif((float)l * (1.0f / 1024.0f), &s, &cg);
    float2 om  = make_float2(cg, -s);
    float2 den = make_float2(1.f + om.x, om.y);
    float  dn  = den.x * den.x + den.y * den.y;
    float2 num = make_float2(1.f - om.x, -om.y);
    float zx = 2.f * (num.x * den.x + num.y * den.y) / dn;
    float zy = 2.f * (num.y * den.x - num.x * den.y) / dn;
    float2 fac = make_float2(2.f * den.x / dn, -2.f * den.y / dn);
    float z2x = zx * zx - zy * zy;
    float z2y = 2.f * zx * zy;

    unsigned long long A0[16], A1[16];
    unsigned long long A0q = 0ULL, A1q = 0ULL;
    #pragma unroll
    for (int j = 0; j < 16; ++j) { A0[j] = 0ULL; A1[j] = 0ULL; }

    #pragma unroll
    for (int n = 0; n < NN; ++n) {
        float4 W = sW4[n];
        float Dx = z2x + W.z - 2.f * W.x * zx;
        float Dy = z2y - 2.f * W.x * zy;
        float ir = 1.f / (Dx * Dx + Dy * Dy);
        float ivx = Dx * ir, ivy = -Dy * ir;          // 1/D
        float ax = zx - W.x;                          // z - wr
        float alr = 2.f * (ax * ivx - zy * ivy);
        float ali = 2.f * (ax * ivy + zy * ivx);
        float ber = -2.f * W.y * ivx;
        float bei = -2.f * W.y * ivy;
        unsigned long long ALPHA = pack2(alr, ali);
        unsigned long long BETA  = pack2(ber, bei);
        #pragma unroll
        for (int j = 0; j < 16; ++j) {
            union { float4 f; unsigned long long u64[2]; } c1, c2;
            c1.f = sT1[j][n];
            c2.f = sT2[j][n];
            A0[j] = fma2(c1.u64[0], ALPHA, A0[j]);
            A0[j] = fma2(c1.u64[1], BETA,  A0[j]);
            A1[j] = fma2(c2.u64[0], ALPHA, A1[j]);
            A1[j] = fma2(c2.u64[1], BETA,  A1[j]);
        }
        float4 q = sQ[n];
        A0q = fma2(pack2(q.x, q.x), ALPHA, A0q);
        A0q = fma2(pack2(q.y, q.y), BETA,  A0q);
        A1q = fma2(pack2(q.z, q.z), ALPHA, A1q);
    }

    float2 r0q, r1q;
    unpack2(A0q, r0q.x, r0q.y);
    unpack2(A1q, r1q.x, r1q.y);
    r0q.x *= dt; r0q.y *= dt; r1q.x *= dt; r1q.y *= dt;
    float2 onep = make_float2(1.f + r1q.x, r1q.y);
    float  oin  = 1.f / (onep.x * onep.x + onep.y * onep.y);
    float2 coef = cmulf(r0q, make_float2(onep.x * oin, -onep.y * oin)); // r0q/(1+r1q)

    #pragma unroll
    for (int j = 0; j < 16; ++j) {
        float2 a0j, a1j;
        unpack2(A0[j], a0j.x, a0j.y);
        unpack2(A1[j], a1j.x, a1j.y);
        float2 R0 = make_float2(a0j.x * dt, a0j.y * dt);
        float2 R1 = make_float2(a1j.x * dt, a1j.y * dt);
        float2 corr = cmulf(coef, R1);
        float2 kf = cmulf(csubf(R0, corr), fac);
        g_kf[((c0 + j) * HH + h) * LF + l] = kf;
    }
}

// ---------------- odd bins of the 4096-DFT of the kernel ----------------
// 2-channel complex packing + premod-fused second FFT. (R11-proven)
__global__ __launch_bounds__(256, 3) void k_kernelfft() {
    __shared__ float sre[2 * PADN], sim[2 * PADN];
    int s = threadIdx.x >> 7, u = threadIdx.x & 127;
    int p = blockIdx.x * 2 + s;                       // pair index in [0, 4096)
    int c1 = (p >> 8) * 2;                            // even channel
    int h  = p & 255;
    int ch1 = c1 * HH + h;
    int ch2 = ch1 + HH;                               // channel c1+1, same h
    float* re = sre + s * PADN;
    float* im = sim + s * PADN;

    const float2* kf1 = g_kf + (size_t)ch1 * LF;
    const float2* kf2 = g_kf + (size_t)ch2 * LF;
    for (int i = u; i <= 1024; i += 128) {
        float2 X1 = kf1[i];
        float2 X2 = kf2[i];
        re[PIX(i)] = X1.x - X2.y;                     // Z = X1 + i*X2
        im[PIX(i)] = X1.y + X2.x;
        if (i >= 1 && i < 1024) {
            int m = 2048 - i;                         // conj(X1) + i*conj(X2)
            re[PIX(m)] = X1.x + X2.y;
            im[PIX(m)] = X2.x - X1.y;
        }
    }
    fft2048<1, 0>(re, im, u);                         // z = (k1 + i*k2) * 2048
    fft2048<0, 1>(re, im, u, 1.0f / 2048.0f);         // Y = FFT(z/2048 * e^{-i*pi*l/2048})
    float2* d1 = g_kodd + (size_t)ch1 * 1024;
    float2* d2 = g_kodd + (size_t)ch2 * 1024;
    for (int j = u; j < 1024; j += 128) {
        int pj = PIX(j), pm = PIX(2047 - j);
        float Pr = re[pj], Pi = im[pj];
        float Mr = re[pm], Mi = im[pm];
        d1[j] = make_float2(0.5f * (Pr + Mr), 0.5f * (Pi - Mi));
        d2[j] = make_float2(0.5f * (Pi + Mi), 0.5f * (Mr - Pr));
    }
}

// ---------------- rfft(pd, 4096) via real packing (2 rows/block) ----------------
__global__ __launch_bounds__(256, 3) void k_pdfft(const float* __restrict__ pd) {
    __shared__ float sre[2 * PADN], sim[2 * PADN];
    int s = threadIdx.x >> 7, u = threadIdx.x & 127;
    int ch = blockIdx.x * 2 + s;                      // b*256 + h
    float* re = sre + s * PADN;
    float* im = sim + s * PADN;

    const float* src = pd + (size_t)ch * LL;
    for (int n = u; n < 2048; n += 128) {
        if (n < 1024) { re[PIX(n)] = src[2 * n]; im[PIX(n)] = src[2 * n + 1]; }
        else          { re[PIX(n)] = 0.f;        im[PIX(n)] = 0.f; }
    }
    fft2048<0, 0>(re, im, u);
    float2* dst = g_pdf + (size_t)ch * 2049;
    for (int k = u; k < 2048; k += 128) {
        float2 Yk = make_float2(re[PIX(k)], im[PIX(k)]);
        int km = (2048 - k) & 2047;
        float2 Ym = make_float2(re[PIX(km)], im[PIX(km)]);
        float2 E = make_float2(0.5f * (Yk.x + Ym.x), 0.5f * (Yk.y - Ym.y));
        float2 D = make_float2(Yk.x - Ym.x, Yk.y + Ym.y);
        float2 O = make_float2(0.5f * D.y, -0.5f * D.x);
        float2 w = g_tw[k];
        dst[k] = caddf(E, cmulf(w, O));
    }
    if (u == 0) {
        float2 Y0 = make_float2(re[PIX(0)], im[PIX(0)]);
        dst[2048] = make_float2(Y0.x - Y0.y, 0.f);
    }
}

// ---------------- conv: grid (HH, CSPLIT); spectral build fused into iFFT stage-0 ----------------
// k = u + 128m has the parity of u for all m -> one-time base pointer select per thread;
// all K loads coalesced. Eliminates one smem round (32 STS + 32 LDS) + 1 sync per channel.
__global__ __launch_bounds__(256, 3) void k_conv() {
    extern __shared__ char smraw[];
    float*  sre = (float*)smraw;                 // 2*PADN
    float*  sim = sre + 2 * PADN;                // 2*PADN
    float2* sPD = (float2*)(sim + 2 * PADN);     // 2*2049
    int tid = threadIdx.x, s = tid >> 7, u = tid & 127;   // s = batch
    int h = blockIdx.x;
    int split = blockIdx.y;
    float* re = sre + s * PADN;
    float* im = sim + s * PADN;

    for (int b = 0; b < NBATCH; ++b) {
        const float2* pf = g_pdf + ((size_t)b * HH + h) * 2049;
        for (int m = tid; m < 2049; m += 256) sPD[b * 2049 + m] = pf[m];
    }
    float racc0[8], racc1[8];
    #pragma unroll
    for (int i = 0; i < 8; ++i) { racc0[i] = 0.f; racc1[i] = 0.f; }
    __syncthreads();

    const float2* sPDs = sPD + s * 2049;
    int i0   = u >> 1;
    int mir0 = (u & 1) ? (1023 - i0) : (1024 - i0);
    int cbeg = split * (CCHN / CSPLIT);

    for (int ci = 0; ci < CCHN / CSPLIT; ++ci) {
        int c = cbeg + ci;
        const float2* kf = g_kf   + ((size_t)c * HH + h) * LF;
        const float2* ko = g_kodd + ((size_t)c * HH + h) * 1024;
        const float2* base = (u & 1) ? ko : kf;

        // ---- stage 0 (fused spectral build): x[m] = Y[u+128m], then dft16 ----
        float2 x[16];
        #pragma unroll
        for (int m = 0; m < 16; ++m) {
            int k = u + 128 * m;
            float2 Ka = base[i0 + 64 * m];            // K[k]
            float2 Kb = base[mir0 - 64 * m];          // K[2048-k]
            float2 Xk = cmulf(sPDs[k],        Ka);
            float2 X2 = cmulf(sPDs[2048 - k], Kb);
            float2 E = make_float2(0.5f * (Xk.x + X2.x), 0.5f * (Xk.y - X2.y));
            float2 D = make_float2(Xk.x - X2.x, Xk.y + X2.y);
            float2 w = g_tw[k];
            float2 O = make_float2(0.5f * (D.x * w.x + D.y * w.y),
                                   0.5f * (D.y * w.x - D.x * w.y));   // (D/2)*conj(w)
            x[m] = make_float2(E.x - O.y, E.y + O.x);                 // Y = E + i*O
        }
        dft16(x, 1);
        #pragma unroll
        for (int m = 0; m < 16; ++m) {
            int d = 16 * u + m, i = PIX(d);
            float2 v = x[((m & 3) << 2) | (m >> 2)];
            re[i] = v.x; im[i] = v.y;
        }
        __syncthreads();

        // ---- stage 1 ----
        #pragma unroll
        for (int m = 0; m < 16; ++m) { int a = u + 128 * m, i = PIX(a); x[m] = make_float2(re[i], im[i]); }
        {
            int p = u & 15;
            float2 w = g_tw[16 * p];
            w.y = -w.y;                               // inverse
            float2 cur = w;
            #pragma unroll
            for (int m = 1; m < 16; ++m) { x[m] = cmulf(x[m], cur); cur = cmulf(cur, w); }
        }
        dft16(x, 1);
        __syncthreads();
        {
            int basei = ((u >> 4) << 8) + (u & 15);
            #pragma unroll
            for (int m = 0; m < 16; ++m) {
                int d = basei + 16 * m, i = PIX(d);
                float2 v = x[((m & 3) << 2) | (m >> 2)];
                re[i] = v.x; im[i] = v.y;
            }
        }
        __syncthreads();

        // ---- stage 2 ----
        float2 e[8], f[8];
        #pragma unroll
        for (int m = 0; m < 8; ++m) {
            int a0 = u + 256 * m, a1 = u + 128 + 256 * m;
            e[m] = make_float2(re[PIX(a0)], im[PIX(a0)]);
            f[m] = make_float2(re[PIX(a1)], im[PIX(a1)]);
        }
        {
            float2 w0 = g_tw[2 * u], w1 = g_tw[2 * (u + 128)];
            w0.y = -w0.y; w1.y = -w1.y;               // inverse
            float2 c0 = w0, c1 = w1;
            #pragma unroll
            for (int m = 1; m < 8; ++m) {
                e[m] = cmulf(e[m], c0); c0 = cmulf(c0, w0);
                f[m] = cmulf(f[m], c1); c1 = cmulf(c1, w1);
            }
        }
        dft8(e, 1); dft8(f, 1);
        __syncthreads();
        #pragma unroll
        for (int m = 0; m < 8; ++m) {
            int d0 = u + 256 * m, d1 = u + 128 + 256 * m;
            re[PIX(d0)] = e[m].x; im[PIX(d0)] = e[m].y;
            re[PIX(d1)] = f[m].x; im[PIX(d1)] = f[m].y;
        }
        __syncthreads();

        // ---- dC-weighted accumulation ----
        const float* wv = g_dCt + ((size_t)h * CCHN + c) * LL;
        #pragma unroll
        for (int i = 0; i < 8; ++i) {
            int l = tid + 256 * i;
            int pi = PIX(l >> 1);
            float wl = (1.0f / 2048.0f) * wv[l];
            float x0 = (l & 1) ? sim[pi] : sre[pi];
            float x1 = (l & 1) ? sim[PADN + pi] : sre[PADN + pi];
            racc0[i] += x0 * wl;
            racc1[i] += x1 * wl;
        }
        __syncthreads();
    }
    float* p0 = g_part + (((size_t)split * NBATCH + 0) * HH + h) * LL;
    float* p1 = g_part + (((size_t)split * NBATCH + 1) * HH + h) * LL;
    #pragma unroll
    for (int i = 0; i < 8; ++i) {
        int l = tid + 256 * i;
        p0[l] = racc0[i];
        p1[l] = racc1[i];
    }
}

// ---------------- reduce partials -> out ----------------
__global__ void k_reduce(float* __restrict__ out) {
    int i = blockIdx.x * blockDim.x + threadIdx.x;     // over NBATCH*HH*LL
    const int TOT = NBATCH * HH * LL;
    if (i >= TOT) return;
    float v = 0.f;
    #pragma unroll
    for (int sp = 0; sp < CSPLIT; ++sp)
        v += g_part[(size_t)sp * TOT + i];
    out[i] = v;
}

// ---------------- launch ----------------
extern "C" void kernel_launch(void* const* d_in, const int* in_sizes, int n_in,
                              void* d_out, int out_size) {
    const float* log_dt = (const float*)d_in[0];
    const float* B_ri   = (const float*)d_in[1];
    const float* P_ri   = (const float*)d_in[2];
    const float* C_ri   = (const float*)d_in[3];
    const float* iwr    = (const float*)d_in[4];
    const float* wim    = (const float*)d_in[5];
    const float* dC     = (const float*)d_in[6];
    const float* pd     = (const float*)d_in[7];
    float* out = (float*)d_out;
    (void)in_sizes; (void)n_in; (void)out_size;

    const int SM_CONV = (2 * PADN * 2) * (int)sizeof(float)       // sre+sim
                      + 2 * 2049 * (int)sizeof(float2);           // sPD both batches
    cudaFuncSetAttribute(k_conv, cudaFuncAttributeMaxDynamicSharedMemorySize, SM_CONV);

    k_init_tw<<<8, 256>>>();
    k_transpose<<<dim3(LL / 32, HH), 256>>>(dC);
    k_cauchy<<<dim3((LF + 127) / 128, HH, 2), 128>>>(log_dt, B_ri, P_ri, C_ri, iwr, wim);
    k_kernelfft<<<CCHN * HH / 4, 256>>>();
    k_pdfft<<<NBATCH * HH / 2, 256>>>(pd);
    k_conv<<<dim3(HH, CSPLIT), 256, SM_CONV>>>();
    k_reduce<<<(NBATCH * HH * LL + 255) / 256, 256>>>(out);
}

// round 16
// speedup vs baseline: 1.3403x; 1.0626x over previous
#include <cuda_runtime.h>
#include <math.h>

#define HH 256
#define NN 32
#define CCHN 32
#define LL 2048
#define LF 1025
#define NBATCH 2
#define CSPLIT 8
#define PADN 2176                       // 2048 + 128 pad floats
#define PIX(a) ((a) + ((a) >> 4))

// ---------------- scratch ----------------
__device__ float2 g_tw[2048];                 // e^{-2*pi*i*k/4096}
__device__ float2 g_kf  [CCHN * HH * LF];     // (C,H,1025) 2048-DFT of kernel (= even bins of 4096-DFT)
__device__ float2 g_kodd[CCHN * HH * 1024];   // odd bins of 4096-DFT
__device__ float2 g_pdf [NBATCH * HH * 2049]; // rfft(pd, 4096)
__device__ float  g_dCt [HH * CCHN * LL];     // (H,C,L)
__device__ float  g_part[CSPLIT * NBATCH * HH * LL]; // conv partial sums (33.6 MB)

__device__ __forceinline__ float2 cmulf(float2 a, float2 b) {
    return make_float2(a.x * b.x - a.y * b.y, a.x * b.y + a.y * b.x);
}
__device__ __forceinline__ float2 caddf(float2 a, float2 b) { return make_float2(a.x + b.x, a.y + b.y); }
__device__ __forceinline__ float2 csubf(float2 a, float2 b) { return make_float2(a.x - b.x, a.y - b.y); }

// ---- packed f32x2 helpers (sm_103a FFMA2 path, PTX-only) ----
__device__ __forceinline__ unsigned long long fma2(unsigned long long a, unsigned long long b,
                                                   unsigned long long c) {
    unsigned long long d;
    asm("fma.rn.f32x2 %0, %1, %2, %3;" : "=l"(d) : "l"(a), "l"(b), "l"(c));
    return d;
}
__device__ __forceinline__ unsigned long long pack2(float lo, float hi) {
    unsigned long long r;
    asm("mov.b64 %0, {%1, %2};" : "=l"(r) : "f"(lo), "f"(hi));
    return r;
}
__device__ __forceinline__ void unpack2(unsigned long long v, float& lo, float& hi) {
    asm("mov.b64 {%0, %1}, %2;" : "=f"(lo), "=f"(hi) : "l"(v));
}

__global__ void k_init_tw() {
    int i = blockIdx.x * blockDim.x + threadIdx.x;
    if (i < 2048) {
        double a = -M_PI * (double)i / 2048.0;
        g_tw[i] = make_float2((float)cos(a), (float)sin(a));
    }
}

// ---------------- dC transpose: (L,H,C) -> (H,C,L) ----------------
__global__ void k_transpose(const float* __restrict__ dC) {
    __shared__ float t[32][33];
    int h  = blockIdx.y;
    int l0 = blockIdx.x * 32;
    int tid = threadIdx.x;
    int c = tid & 31, r = tid >> 5;
    for (int i = r; i < 32; i += 8)
        t[i][c] = dC[(size_t)(l0 + i) * (HH * NN) + h * NN + c];
    __syncthreads();
    int li = tid & 31, cc = tid >> 5;
    for (int i = cc; i < 32; i += 8)
        g_dCt[((size_t)h * CCHN + i) * LL + l0 + li] = t[li][i];
}

// ---------------- small DFTs in registers ----------------
__device__ __forceinline__ void dft4(float2& a, float2& b, float2& c, float2& d, int inv) {
    float2 A = caddf(a, c), B = csubf(a, c), C = caddf(b, d), D = csubf(b, d);
    a = caddf(A, C); c = csubf(A, C);
    if (!inv) { b = make_float2(B.x + D.y, B.y - D.x); d = make_float2(B.x - D.y, B.y + D.x); }
    else      { b = make_float2(B.x - D.y, B.y + D.x); d = make_float2(B.x + D.y, B.y - D.x); }
}

__device__ __forceinline__ void dft8(float2 x[8], int inv) {
    float2 e0 = x[0], e1 = x[2], e2 = x[4], e3 = x[6];
    float2 o0 = x[1], o1 = x[3], o2 = x[5], o3 = x[7];
    dft4(e0, e1, e2, e3, inv);
    dft4(o0, o1, o2, o3, inv);
    const float r = 0.70710678118654752f;
    float sg = inv ? 1.f : -1.f;
    float2 w1 = make_float2(r, sg * r);
    float2 w2 = make_float2(0.f, sg);
    float2 w3 = make_float2(-r, sg * r);
    o1 = cmulf(o1, w1); o2 = cmulf(o2, w2); o3 = cmulf(o3, w3);
    x[0] = caddf(e0, o0); x[4] = csubf(e0, o0);
    x[1] = caddf(e1, o1); x[5] = csubf(e1, o1);
    x[2] = caddf(e2, o2); x[6] = csubf(e2, o2);
    x[3] = caddf(e3, o3); x[7] = csubf(e3, o3);
}

// 16-pt DFT; output X[k1+4k2] lands at x[4*k1+k2] (use perm on store)
__device__ __forceinline__ void dft16(float2 x[16], int inv) {
    #pragma unroll
    for (int n1 = 0; n1 < 4; ++n1)
        dft4(x[n1], x[n1 + 4], x[n1 + 8], x[n1 + 12], inv);
    const float c1 = 0.92387953251128675f, s1 = 0.38268343236508977f, r = 0.70710678118654752f;
    float sg = inv ? 1.f : -1.f;
    float2 W1 = make_float2(c1,  sg * s1);
    float2 W2 = make_float2(r,   sg * r);
    float2 W3 = make_float2(s1,  sg * c1);
    float2 W4 = make_float2(0.f, sg);
    float2 W6 = make_float2(-r,  sg * r);
    float2 W9 = make_float2(-c1, -sg * s1);
    x[5]  = cmulf(x[5],  W1);
    x[9]  = cmulf(x[9],  W2);
    x[13] = cmulf(x[13], W3);
    x[6]  = cmulf(x[6],  W2);
    x[10] = cmulf(x[10], W4);
    x[14] = cmulf(x[14], W6);
    x[7]  = cmulf(x[7],  W3);
    x[11] = cmulf(x[11], W6);
    x[15] = cmulf(x[15], W9);
    #pragma unroll
    for (int k1 = 0; k1 < 4; ++k1)
        dft4(x[4 * k1], x[4 * k1 + 1], x[4 * k1 + 2], x[4 * k1 + 3], inv);
}

// ---- store stage-0 dft16 result (digit-reversal perm) ----
__device__ __forceinline__ void stage0_store(float* re, float* im, int u, float2 x[16]) {
    #pragma unroll
    for (int m = 0; m < 16; ++m) {
        int d = 16 * u + m, i = PIX(d);
        float2 v = x[((m & 3) << 2) | (m >> 2)];
        re[i] = v.x; im[i] = v.y;
    }
}

// ---- stages 1 & 2 of the 2048-pt FFT (stage-0 result already in smem) ----
template <int INV>
__device__ void fft2048_tail(float* re, float* im, int u) {
    float2 x[16];
    __syncthreads();
    #pragma unroll
    for (int m = 0; m < 16; ++m) { int a = u + 128 * m, i = PIX(a); x[m] = make_float2(re[i], im[i]); }
    {
        int p = u & 15;
        float2 w = g_tw[16 * p];
        if (INV) w.y = -w.y;
        float2 cur = w;
        #pragma unroll
        for (int m = 1; m < 16; ++m) { x[m] = cmulf(x[m], cur); cur = cmulf(cur, w); }
    }
    dft16(x, INV);
    __syncthreads();
    {
        int base = ((u >> 4) << 8) + (u & 15);
        #pragma unroll
        for (int m = 0; m < 16; ++m) {
            int d = base + 16 * m, i = PIX(d);
            float2 v = x[((m & 3) << 2) | (m >> 2)];
            re[i] = v.x; im[i] = v.y;
        }
    }
    __syncthreads();
    float2 e[8], f[8];
    #pragma unroll
    for (int m = 0; m < 8; ++m) {
        int a0 = u + 256 * m, a1 = u + 128 + 256 * m;
        e[m] = make_float2(re[PIX(a0)], im[PIX(a0)]);
        f[m] = make_float2(re[PIX(a1)], im[PIX(a1)]);
    }
    {
        float2 w0 = g_tw[2 * u], w1 = g_tw[2 * (u + 128)];
        if (INV) { w0.y = -w0.y; w1.y = -w1.y; }
        float2 c0 = w0, c1 = w1;
        #pragma unroll
        for (int m = 1; m < 8; ++m) {
            e[m] = cmulf(e[m], c0); c0 = cmulf(c0, w0);
            f[m] = cmulf(f[m], c1); c1 = cmulf(c1, w1);
        }
    }
    dft8(e, INV); dft8(f, INV);
    __syncthreads();
    #pragma unroll
    for (int m = 0; m < 8; ++m) {
        int d0 = u + 256 * m, d1 = u + 128 + 256 * m;
        re[PIX(d0)] = e[m].x; im[PIX(d0)] = e[m].y;
        re[PIX(d1)] = f[m].x; im[PIX(d1)] = f[m].y;
    }
    __syncthreads();
}

// ---------------- full 2048-pt FFT (smem in / smem out) ----------------
template <int INV, int PREMOD>
__device__ void fft2048(float* re, float* im, int u, float scale = 1.0f) {
    float2 x[16];
    __syncthreads();
    #pragma unroll
    for (int m = 0; m < 16; ++m) {
        int a = u + 128 * m, i = PIX(a);
        float2 v = make_float2(re[i], im[i]);
        if (PREMOD) {
            float2 w = g_tw[a];
            v = make_float2(scale * (v.x * w.x - v.y * w.y),
                            scale * (v.x * w.y + v.y * w.x));
        }
        x[m] = v;
    }
    dft16(x, INV);
    __syncthreads();
    stage0_store(re, im, u, x);
    fft2048_tail<INV>(re, im, u);
}

// ---------------- Cauchy + Woodbury -> k_f (C,H,1025) ----------------
// Conjugate-pair collapse (R14-proven); occupancy raised to 5 blocks/SM.
__global__ __launch_bounds__(128, 5) void k_cauchy(
    const float* __restrict__ log_dt, const float* __restrict__ B_ri,
    const float* __restrict__ P_ri,   const float* __restrict__ C_ri,
    const float* __restrict__ iwr,    const float* __restrict__ wim) {
    int h    = blockIdx.y;
    int half = blockIdx.z;
    int c0   = half * 16;
    int tid  = threadIdx.x;
    int l    = blockIdx.x * blockDim.x + tid;

    __shared__ float4 sW4[NN];        // (wr, wi, |w|^2, 0)
    __shared__ float4 sQ[NN];         // (gq0, eq0, gq1, 0)
    __shared__ float4 sT1[16][NN];    // (g0, g0, e0, e0)  B-row
    __shared__ float4 sT2[16][NN];    // (g1, g1, e1, e1)  P-row

    float dt = expf(log_dt[h]);
    if (tid < NN) {
        float2 B = ((const float2*)B_ri)[h * NN + tid];
        float2 P = ((const float2*)P_ri)[h * NN + tid];
        float wr = -expf(iwr[h * NN + tid]) * dt;
        float wi = wim[h * NN + tid] * dt;
        sW4[tid] = make_float4(wr, wi, wr * wr + wi * wi, 0.f);
        sQ[tid] = make_float4(B.x * P.x + B.y * P.y,
                              B.y * P.x - B.x * P.y,
                              P.x * P.x + P.y * P.y, 0.f);
    }
    for (int i = tid; i < 16 * NN; i += blockDim.x) {
        int j = i / NN, n = i % NN;
        float2 C = ((const float2*)C_ri)[(c0 + j) * (HH * NN) + h * NN + n];
        float2 B = ((const float2*)B_ri)[h * NN + n];
        float2 P = ((const float2*)P_ri)[h * NN + n];
        float g0 = B.x * C.x - B.y * C.y, e0 = B.x * C.y + B.y * C.x;
        float g1 = P.x * C.x - P.y * C.y, e1 = P.x * C.y + P.y * C.x;
        sT1[j][n] = make_float4(g0, g0, e0, e0);
        sT2[j][n] = make_float4(g1, g1, e1, e1);
    }
    __syncthreads();

    if (l >= LF) return;

    if (l == LL / 2) {
        #pragma unroll
        for (int j = 0; j < 16; ++j) {
            float acc = 0.f;
            #pragma unroll
            for (int n = 0; n < NN; ++n)
                acc += sT1[j][n].x;
            g_kf[((c0 + j) * HH + h) * LF + l] = make_float2(dt * acc, 0.f);
        }
        return;
    }

    float s, cg;
    sincospif((float)l * (1.0f / 1024.0f), &s, &cg);
    float2 om  = make_float2(cg, -s);
    float2 den = make_float2(1.f + om.x, om.y);
    float  dn  = den.x * den.x + den.y * den.y;
    float2 num = make_float2(1.f - om.x, -om.y);
    float zx = 2.f * (num.x * den.x + num.y * den.y) / dn;
    float zy = 2.f * (num.y * den.x - num.x * den.y) / dn;
    float2 fac = make_float2(2.f * den.x / dn, -2.f * den.y / dn);
    float z2x = zx * zx - zy * zy;
    float z2y = 2.f * zx * zy;

    unsigned long long A0[16], A1[16];
    unsigned long long A0q = 0ULL, A1q = 0ULL;
    #pragma unroll
    for (int j = 0; j < 16; ++j) { A0[j] = 0ULL; A1[j] = 0ULL; }

    #pragma unroll
    for (int n = 0; n < NN; ++n) {
        float4 W = sW4[n];
        float Dx = z2x + W.z - 2.f * W.x * zx;
        float Dy = z2y - 2.f * W.x * zy;
        float ir = 1.f / (Dx * Dx + Dy * Dy);
        float ivx = Dx * ir, ivy = -Dy * ir;          // 1/D
        float ax = zx - W.x;                          // z - wr
        float alr = 2.f * (ax * ivx - zy * ivy);
        float ali = 2.f * (ax * ivy + zy * ivx);
        float ber = -2.f * W.y * ivx;
        float bei = -2.f * W.y * ivy;
        unsigned long long ALPHA = pack2(alr, ali);
        unsigned long long BETA  = pack2(ber, bei);
        #pragma unroll
        for (int j = 0; j < 16; ++j) {
            union { float4 f; unsigned long long u64[2]; } c1, c2;
            c1.f = sT1[j][n];
            c2.f = sT2[j][n];
            A0[j] = fma2(c1.u64[0], ALPHA, A0[j]);
            A0[j] = fma2(c1.u64[1], BETA,  A0[j]);
            A1[j] = fma2(c2.u64[0], ALPHA, A1[j]);
            A1[j] = fma2(c2.u64[1], BETA,  A1[j]);
        }
        float4 q = sQ[n];
        A0q = fma2(pack2(q.x, q.x), ALPHA, A0q);
        A0q = fma2(pack2(q.y, q.y), BETA,  A0q);
        A1q = fma2(pack2(q.z, q.z), ALPHA, A1q);
    }

    float2 r0q, r1q;
    unpack2(A0q, r0q.x, r0q.y);
    unpack2(A1q, r1q.x, r1q.y);
    r0q.x *= dt; r0q.y *= dt; r1q.x *= dt; r1q.y *= dt;
    float2 onep = make_float2(1.f + r1q.x, r1q.y);
    float  oin  = 1.f / (onep.x * onep.x + onep.y * onep.y);
    float2 coef = cmulf(r0q, make_float2(onep.x * oin, -onep.y * oin)); // r0q/(1+r1q)

    #pragma unroll
    for (int j = 0; j < 16; ++j) {
        float2 a0j, a1j;
        unpack2(A0[j], a0j.x, a0j.y);
        unpack2(A1[j], a1j.x, a1j.y);
        float2 R0 = make_float2(a0j.x * dt, a0j.y * dt);
        float2 R1 = make_float2(a1j.x * dt, a1j.y * dt);
        float2 corr = cmulf(coef, R1);
        float2 kf = cmulf(csubf(R0, corr), fac);
        g_kf[((c0 + j) * HH + h) * LF + l] = kf;
    }
}

// ---------------- odd bins of the 4096-DFT of the kernel ----------------
// 2-channel complex packing; Hermitian input build fused into the first iFFT's stage-0.
__global__ __launch_bounds__(256, 3) void k_kernelfft() {
    __shared__ float sre[2 * PADN], sim[2 * PADN];
    int s = threadIdx.x >> 7, u = threadIdx.x & 127;
    int p = blockIdx.x * 2 + s;                       // pair index in [0, 4096)
    int c1 = (p >> 8) * 2;                            // even channel
    int h  = p & 255;
    int ch1 = c1 * HH + h;
    int ch2 = ch1 + HH;                               // channel c1+1, same h
    float* re = sre + s * PADN;
    float* im = sim + s * PADN;

    const float2* kf1 = g_kf + (size_t)ch1 * LF;
    const float2* kf2 = g_kf + (size_t)ch2 * LF;

    // ---- first iFFT, stage-0 fused: x[m] = Z[u+128m] built from g_kf ----
    {
        float2 x[16];
        #pragma unroll
        for (int m = 0; m < 16; ++m) {
            int a = u + 128 * m;
            bool mir = (a > 1024);
            int idx = mir ? (2048 - a) : a;
            float2 X1 = kf1[idx];
            float2 X2 = kf2[idx];
            x[m] = mir ? make_float2(X1.x + X2.y, X2.x - X1.y)   // conj(X1)+i*conj(X2)
                       : make_float2(X1.x - X2.y, X1.y + X2.x);  // X1 + i*X2
        }
        dft16(x, 1);
        stage0_store(re, im, u, x);
    }
    fft2048_tail<1>(re, im, u);                       // z = (k1 + i*k2) * 2048
    fft2048<0, 1>(re, im, u, 1.0f / 2048.0f);         // Y = FFT(z/2048 * e^{-i*pi*l/2048})

    float2* d1 = g_kodd + (size_t)ch1 * 1024;
    float2* d2 = g_kodd + (size_t)ch2 * 1024;
    for (int j = u; j < 1024; j += 128) {
        int pj = PIX(j), pm = PIX(2047 - j);
        float Pr = re[pj], Pi = im[pj];
        float Mr = re[pm], Mi = im[pm];
        d1[j] = make_float2(0.5f * (Pr + Mr), 0.5f * (Pi - Mi));
        d2[j] = make_float2(0.5f * (Pi + Mi), 0.5f * (Mr - Pr));
    }
}

// ---------------- rfft(pd, 4096) via real packing (2 rows/block) ----------------
__global__ __launch_bounds__(256, 3) void k_pdfft(const float* __restrict__ pd) {
    __shared__ float sre[2 * PADN], sim[2 * PADN];
    int s = threadIdx.x >> 7, u = threadIdx.x & 127;
    int ch = blockIdx.x * 2 + s;                      // b*256 + h
    float* re = sre + s * PADN;
    float* im = sim + s * PADN;

    const float* src = pd + (size_t)ch * LL;
    for (int n = u; n < 2048; n += 128) {
        if (n < 1024) { re[PIX(n)] = src[2 * n]; im[PIX(n)] = src[2 * n + 1]; }
        else          { re[PIX(n)] = 0.f;        im[PIX(n)] = 0.f; }
    }
    fft2048<0, 0>(re, im, u);
    float2* dst = g_pdf + (size_t)ch * 2049;
    for (int k = u; k < 2048; k += 128) {
        float2 Yk = make_float2(re[PIX(k)], im[PIX(k)]);
        int km = (2048 - k) & 2047;
        float2 Ym = make_float2(re[PIX(km)], im[PIX(km)]);
        float2 E = make_float2(0.5f * (Yk.x + Ym.x), 0.5f * (Yk.y - Ym.y));
        float2 D = make_float2(Yk.x - Ym.x, Yk.y + Ym.y);
        float2 O = make_float2(0.5f * D.y, -0.5f * D.x);
        float2 w = g_tw[k];
        dst[k] = caddf(E, cmulf(w, O));
    }
    if (u == 0) {
        float2 Y0 = make_float2(re[PIX(0)], im[PIX(0)]);
        dst[2048] = make_float2(Y0.x - Y0.y, 0.f);
    }
}

// ---------------- conv: grid (HH, CSPLIT); spectral build fused into iFFT stage-0 ----------------
__global__ __launch_bounds__(256, 3) void k_conv() {
    extern __shared__ char smraw[];
    float*  sre = (float*)smraw;                 // 2*PADN
    float*  sim = sre + 2 * PADN;                // 2*PADN
    float2* sPD = (float2*)(sim + 2 * PADN);     // 2*2049
    int tid = threadIdx.x, s = tid >> 7, u = tid & 127;   // s = batch
    int h = blockIdx.x;
    int split = blockIdx.y;
    float* re = sre + s * PADN;
    float* im = sim + s * PADN;

    for (int b = 0; b < NBATCH; ++b) {
        const float2* pf = g_pdf + ((size_t)b * HH + h) * 2049;
        for (int m = tid; m < 2049; m += 256) sPD[b * 2049 + m] = pf[m];
    }
    float racc0[8], racc1[8];
    #pragma unroll
    for (int i = 0; i < 8; ++i) { racc0[i] = 0.f; racc1[i] = 0.f; }
    __syncthreads();

    const float2* sPDs = sPD + s * 2049;
    int i0   = u >> 1;
    int mir0 = (u & 1) ? (1023 - i0) : (1024 - i0);
    int cbeg = split * (CCHN / CSPLIT);

    for (int ci = 0; ci < CCHN / CSPLIT; ++ci) {
        int c = cbeg + ci;
        const float2* kf = g_kf   + ((size_t)c * HH + h) * LF;
        const float2* ko = g_kodd + ((size_t)c * HH + h) * 1024;
        const float2* base = (u & 1) ? ko : kf;

        // ---- stage 0 (fused spectral build) ----
        float2 x[16];
        #pragma unroll
        for (int m = 0; m < 16; ++m) {
            int k = u + 128 * m;
            float2 Ka = base[i0 + 64 * m];            // K[k]
            float2 Kb = base[mir0 - 64 * m];          // K[2048-k]
            float2 Xk = cmulf(sPDs[k],        Ka);
            float2 X2 = cmulf(sPDs[2048 - k], Kb);
            float2 E = make_float2(0.5f * (Xk.x + X2.x), 0.5f * (Xk.y - X2.y));
            float2 D = make_float2(Xk.x - X2.x, Xk.y + X2.y);
            float2 w = g_tw[k];
            float2 O = make_float2(0.5f * (D.x * w.x + D.y * w.y),
                                   0.5f * (D.y * w.x - D.x * w.y));   // (D/2)*conj(w)
            x[m] = make_float2(E.x - O.y, E.y + O.x);                 // Y = E + i*O
        }
        dft16(x, 1);
        stage0_store(re, im, u, x);
        fft2048_tail<1>(re, im, u);

        // ---- dC-weighted accumulation ----
        const float* wv = g_dCt + ((size_t)h * CCHN + c) * LL;
        #pragma unroll
        for (int i = 0; i < 8; ++i) {
            int l = tid + 256 * i;
            int pi = PIX(l >> 1);
            float wl = (1.0f / 2048.0f) * wv[l];
            float x0 = (l & 1) ? sim[pi] : sre[pi];
            float x1 = (l & 1) ? sim[PADN + pi] : sre[PADN + pi];
            racc0[i] += x0 * wl;
            racc1[i] += x1 * wl;
        }
        __syncthreads();
    }
    float* p0 = g_part + (((size_t)split * NBATCH + 0) * HH + h) * LL;
    float* p1 = g_part + (((size_t)split * NBATCH + 1) * HH + h) * LL;
    #pragma unroll
    for (int i = 0; i < 8; ++i) {
        int l = tid + 256 * i;
        p0[l] = racc0[i];
        p1[l] = racc1[i];
    }
}

// ---------------- reduce partials -> out ----------------
__global__ void k_reduce(float* __restrict__ out) {
    int i = blockIdx.x * blockDim.x + threadIdx.x;     // over NBATCH*HH*LL
    const int TOT = NBATCH * HH * LL;
    if (i >= TOT) return;
    float v = 0.f;
    #pragma unroll
    for (int sp = 0; sp < CSPLIT; ++sp)
        v += g_part[(size_t)sp * TOT + i];
    out[i] = v;
}

// ---------------- launch ----------------
extern "C" void kernel_launch(void* const* d_in, const int* in_sizes, int n_in,
                              void* d_out, int out_size) {
    const float* log_dt = (const float*)d_in[0];
    const float* B_ri   = (const float*)d_in[1];
    const float* P_ri   = (const float*)d_in[2];
    const float* C_ri   = (const float*)d_in[3];
    const float* iwr    = (const float*)d_in[4];
    const float* wim    = (const float*)d_in[5];
    const float* dC     = (const float*)d_in[6];
    const float* pd     = (const float*)d_in[7];
    float* out = (float*)d_out;
    (void)in_sizes; (void)n_in; (void)out_size;

    const int SM_CONV = (2 * PADN * 2) * (int)sizeof(float)       // sre+sim
                      + 2 * 2049 * (int)sizeof(float2);           // sPD both batches
    cudaFuncSetAttribute(k_conv, cudaFuncAttributeMaxDynamicSharedMemorySize, SM_CONV);

    k_init_tw<<<8, 256>>>();
    k_transpose<<<dim3(LL / 32, HH), 256>>>(dC);
    k_cauchy<<<dim3((LF + 127) / 128, HH, 2), 128>>>(log_dt, B_ri, P_ri, C_ri, iwr, wim);
    k_kernelfft<<<CCHN * HH / 4, 256>>>();
    k_pdfft<<<NBATCH * HH / 2, 256>>>(pd);
    k_conv<<<dim3(HH, CSPLIT), 256, SM_CONV>>>();
    k_reduce<<<(NBATCH * HH * LL + 255) / 256, 256>>>(out);
}

// round 17
// speedup vs baseline: 1.4120x; 1.0535x over previous
#include <cuda_runtime.h>
#include <math.h>

#define HH 256
#define NN 32
#define CCHN 32
#define LL 2048
#define LF 1025
#define NBATCH 2
#define CSPLIT 8
#define PADN 2176                       // 2048 + 128 pad floats
#define PIX(a) ((a) + ((a) >> 4))

// ---------------- scratch ----------------
__device__ float2 g_tw[2048];                 // e^{-2*pi*i*k/4096}
__device__ float2 g_kf  [CCHN * HH * LF];     // (C,H,1025) 2048-DFT of kernel (= even bins of 4096-DFT)
__device__ float2 g_kodd[CCHN * HH * 1024];   // odd bins of 4096-DFT
__device__ float2 g_pdf [NBATCH * HH * 2049]; // rfft(pd, 4096)
__device__ float  g_dCt [HH * CCHN * LL];     // (H,C,L)
__device__ float  g_part[CSPLIT * NBATCH * HH * LL]; // conv partial sums (33.6 MB)

__device__ __forceinline__ float2 cmulf(float2 a, float2 b) {
    return make_float2(a.x * b.x - a.y * b.y, a.x * b.y + a.y * b.x);
}
__device__ __forceinline__ float2 caddf(float2 a, float2 b) { return make_float2(a.x + b.x, a.y + b.y); }
__device__ __forceinline__ float2 csubf(float2 a, float2 b) { return make_float2(a.x - b.x, a.y - b.y); }

// ---- packed f32x2 helpers (sm_103a FFMA2 path, PTX-only) ----
__device__ __forceinline__ unsigned long long fma2(unsigned long long a, unsigned long long b,
                                                   unsigned long long c) {
    unsigned long long d;
    asm("fma.rn.f32x2 %0, %1, %2, %3;" : "=l"(d) : "l"(a), "l"(b), "l"(c));
    return d;
}
__device__ __forceinline__ unsigned long long pack2(float lo, float hi) {
    unsigned long long r;
    asm("mov.b64 %0, {%1, %2};" : "=l"(r) : "f"(lo), "f"(hi));
    return r;
}
__device__ __forceinline__ void unpack2(unsigned long long v, float& lo, float& hi) {
    asm("mov.b64 {%0, %1}, %2;" : "=f"(lo), "=f"(hi) : "l"(v));
}

__global__ void k_init_tw() {
    int i = blockIdx.x * blockDim.x + threadIdx.x;
    if (i < 2048) {
        double a = -M_PI * (double)i / 2048.0;
        g_tw[i] = make_float2((float)cos(a), (float)sin(a));
    }
}

// ---------------- dC transpose: (L,H,C) -> (H,C,L) ----------------
__global__ void k_transpose(const float* __restrict__ dC) {
    __shared__ float t[32][33];
    int h  = blockIdx.y;
    int l0 = blockIdx.x * 32;
    int tid = threadIdx.x;
    int c = tid & 31, r = tid >> 5;
    for (int i = r; i < 32; i += 8)
        t[i][c] = dC[(size_t)(l0 + i) * (HH * NN) + h * NN + c];
    __syncthreads();
    int li = tid & 31, cc = tid >> 5;
    for (int i = cc; i < 32; i += 8)
        g_dCt[((size_t)h * CCHN + i) * LL + l0 + li] = t[li][i];
}

// ---------------- small DFTs in registers ----------------
__device__ __forceinline__ void dft4(float2& a, float2& b, float2& c, float2& d, int inv) {
    float2 A = caddf(a, c), B = csubf(a, c), C = caddf(b, d), D = csubf(b, d);
    a = caddf(A, C); c = csubf(A, C);
    if (!inv) { b = make_float2(B.x + D.y, B.y - D.x); d = make_float2(B.x - D.y, B.y + D.x); }
    else      { b = make_float2(B.x - D.y, B.y + D.x); d = make_float2(B.x + D.y, B.y - D.x); }
}

__device__ __forceinline__ void dft8(float2 x[8], int inv) {
    float2 e0 = x[0], e1 = x[2], e2 = x[4], e3 = x[6];
    float2 o0 = x[1], o1 = x[3], o2 = x[5], o3 = x[7];
    dft4(e0, e1, e2, e3, inv);
    dft4(o0, o1, o2, o3, inv);
    const float r = 0.70710678118654752f;
    float sg = inv ? 1.f : -1.f;
    float2 w1 = make_float2(r, sg * r);
    float2 w2 = make_float2(0.f, sg);
    float2 w3 = make_float2(-r, sg * r);
    o1 = cmulf(o1, w1); o2 = cmulf(o2, w2); o3 = cmulf(o3, w3);
    x[0] = caddf(e0, o0); x[4] = csubf(e0, o0);
    x[1] = caddf(e1, o1); x[5] = csubf(e1, o1);
    x[2] = caddf(e2, o2); x[6] = csubf(e2, o2);
    x[3] = caddf(e3, o3); x[7] = csubf(e3, o3);
}

// 16-pt DFT; output X[k1+4k2] lands at x[4*k1+k2] (use perm on store)
__device__ __forceinline__ void dft16(float2 x[16], int inv) {
    #pragma unroll
    for (int n1 = 0; n1 < 4; ++n1)
        dft4(x[n1], x[n1 + 4], x[n1 + 8], x[n1 + 12], inv);
    const float c1 = 0.92387953251128675f, s1 = 0.38268343236508977f, r = 0.70710678118654752f;
    float sg = inv ? 1.f : -1.f;
    float2 W1 = make_float2(c1,  sg * s1);
    float2 W2 = make_float2(r,   sg * r);
    float2 W3 = make_float2(s1,  sg * c1);
    float2 W4 = make_float2(0.f, sg);
    float2 W6 = make_float2(-r,  sg * r);
    float2 W9 = make_float2(-c1, -sg * s1);
    x[5]  = cmulf(x[5],  W1);
    x[9]  = cmulf(x[9],  W2);
    x[13] = cmulf(x[13], W3);
    x[6]  = cmulf(x[6],  W2);
    x[10] = cmulf(x[10], W4);
    x[14] = cmulf(x[14], W6);
    x[7]  = cmulf(x[7],  W3);
    x[11] = cmulf(x[11], W6);
    x[15] = cmulf(x[15], W9);
    #pragma unroll
    for (int k1 = 0; k1 < 4; ++k1)
        dft4(x[4 * k1], x[4 * k1 + 1], x[4 * k1 + 2], x[4 * k1 + 3], inv);
}

// ---- store stage-0 dft16 result (digit-reversal perm) ----
__device__ __forceinline__ void stage0_store(float* re, float* im, int u, float2 x[16]) {
    #pragma unroll
    for (int m = 0; m < 16; ++m) {
        int d = 16 * u + m, i = PIX(d);
        float2 v = x[((m & 3) << 2) | (m >> 2)];
        re[i] = v.x; im[i] = v.y;
    }
}

// ---- stages 1 & 2 of the 2048-pt FFT (stage-0 result already in smem) ----
template <int INV>
__device__ void fft2048_tail(float* re, float* im, int u) {
    float2 x[16];
    __syncthreads();
    #pragma unroll
    for (int m = 0; m < 16; ++m) { int a = u + 128 * m, i = PIX(a); x[m] = make_float2(re[i], im[i]); }
    {
        int p = u & 15;
        float2 w = g_tw[16 * p];
        if (INV) w.y = -w.y;
        float2 cur = w;
        #pragma unroll
        for (int m = 1; m < 16; ++m) { x[m] = cmulf(x[m], cur); cur = cmulf(cur, w); }
    }
    dft16(x, INV);
    __syncthreads();
    {
        int base = ((u >> 4) << 8) + (u & 15);
        #pragma unroll
        for (int m = 0; m < 16; ++m) {
            int d = base + 16 * m, i = PIX(d);
            float2 v = x[((m & 3) << 2) | (m >> 2)];
            re[i] = v.x; im[i] = v.y;
        }
    }
    __syncthreads();
    float2 e[8], f[8];
    #pragma unroll
    for (int m = 0; m < 8; ++m) {
        int a0 = u + 256 * m, a1 = u + 128 + 256 * m;
        e[m] = make_float2(re[PIX(a0)], im[PIX(a0)]);
        f[m] = make_float2(re[PIX(a1)], im[PIX(a1)]);
    }
    {
        float2 w0 = g_tw[2 * u], w1 = g_tw[2 * (u + 128)];
        if (INV) { w0.y = -w0.y; w1.y = -w1.y; }
        float2 c0 = w0, c1 = w1;
        #pragma unroll
        for (int m = 1; m < 8; ++m) {
            e[m] = cmulf(e[m], c0); c0 = cmulf(c0, w0);
            f[m] = cmulf(f[m], c1); c1 = cmulf(c1, w1);
        }
    }
    dft8(e, INV); dft8(f, INV);
    __syncthreads();
    #pragma unroll
    for (int m = 0; m < 8; ++m) {
        int d0 = u + 256 * m, d1 = u + 128 + 256 * m;
        re[PIX(d0)] = e[m].x; im[PIX(d0)] = e[m].y;
        re[PIX(d1)] = f[m].x; im[PIX(d1)] = f[m].y;
    }
    __syncthreads();
}

// ---------------- full 2048-pt FFT (smem in / smem out) ----------------
template <int INV, int PREMOD>
__device__ void fft2048(float* re, float* im, int u, float scale = 1.0f) {
    float2 x[16];
    __syncthreads();
    #pragma unroll
    for (int m = 0; m < 16; ++m) {
        int a = u + 128 * m, i = PIX(a);
        float2 v = make_float2(re[i], im[i]);
        if (PREMOD) {
            float2 w = g_tw[a];
            v = make_float2(scale * (v.x * w.x - v.y * w.y),
                            scale * (v.x * w.y + v.y * w.x));
        }
        x[m] = v;
    }
    dft16(x, INV);
    __syncthreads();
    stage0_store(re, im, u, x);
    fft2048_tail<INV>(re, im, u);
}

// ---------------- Cauchy + Woodbury -> k_f (C,H,1025) ----------------
// Conjugate-pair collapse (R14-proven); occupancy 5 blocks/SM (R16-proven).
__global__ __launch_bounds__(128, 5) void k_cauchy(
    const float* __restrict__ log_dt, const float* __restrict__ B_ri,
    const float* __restrict__ P_ri,   const float* __restrict__ C_ri,
    const float* __restrict__ iwr,    const float* __restrict__ wim) {
    int h    = blockIdx.y;
    int half = blockIdx.z;
    int c0   = half * 16;
    int tid  = threadIdx.x;
    int l    = blockIdx.x * blockDim.x + tid;

    __shared__ float4 sW4[NN];        // (wr, wi, |w|^2, 0)
    __shared__ float4 sQ[NN];         // (gq0, eq0, gq1, 0)
    __shared__ float4 sT1[16][NN];    // (g0, g0, e0, e0)  B-row
    __shared__ float4 sT2[16][NN];    // (g1, g1, e1, e1)  P-row

    float dt = expf(log_dt[h]);
    if (tid < NN) {
        float2 B = ((const float2*)B_ri)[h * NN + tid];
        float2 P = ((const float2*)P_ri)[h * NN + tid];
        float wr = -expf(iwr[h * NN + tid]) * dt;
        float wi = wim[h * NN + tid] * dt;
        sW4[tid] = make_float4(wr, wi, wr * wr + wi * wi, 0.f);
        sQ[tid] = make_float4(B.x * P.x + B.y * P.y,
                              B.y * P.x - B.x * P.y,
                              P.x * P.x + P.y * P.y, 0.f);
    }
    for (int i = tid; i < 16 * NN; i += blockDim.x) {
        int j = i / NN, n = i % NN;
        float2 C = ((const float2*)C_ri)[(c0 + j) * (HH * NN) + h * NN + n];
        float2 B = ((const float2*)B_ri)[h * NN + n];
        float2 P = ((const float2*)P_ri)[h * NN + n];
        float g0 = B.x * C.x - B.y * C.y, e0 = B.x * C.y + B.y * C.x;
        float g1 = P.x * C.x - P.y * C.y, e1 = P.x * C.y + P.y * C.x;
        sT1[j][n] = make_float4(g0, g0, e0, e0);
        sT2[j][n] = make_float4(g1, g1, e1, e1);
    }
    __syncthreads();

    if (l >= LF) return;

    if (l == LL / 2) {
        #pragma unroll
        for (int j = 0; j < 16; ++j) {
            float acc = 0.f;
            #pragma unroll
            for (int n = 0; n < NN; ++n)
                acc += sT1[j][n].x;
            g_kf[((c0 + j) * HH + h) * LF + l] = make_float2(dt * acc, 0.f);
        }
        return;
    }

    float s, cg;
    sincospif((float)l * (1.0f / 1024.0f), &s, &cg);
    float2 om  = make_float2(cg, -s);
    float2 den = make_float2(1.f + om.x, om.y);
    float  dn  = den.x * den.x + den.y * den.y;
    float2 num = make_float2(1.f - om.x, -om.y);
    float zx = 2.f * (num.x * den.x + num.y * den.y) / dn;
    float zy = 2.f * (num.y * den.x - num.x * den.y) / dn;
    float2 fac = make_float2(2.f * den.x / dn, -2.f * den.y / dn);
    float z2x = zx * zx - zy * zy;
    float z2y = 2.f * zx * zy;

    unsigned long long A0[16], A1[16];
    unsigned long long A0q = 0ULL, A1q = 0ULL;
    #pragma unroll
    for (int j = 0; j < 16; ++j) { A0[j] = 0ULL; A1[j] = 0ULL; }

    #pragma unroll
    for (int n = 0; n < NN; ++n) {
        float4 W = sW4[n];
        float Dx = z2x + W.z - 2.f * W.x * zx;
        float Dy = z2y - 2.f * W.x * zy;
        float ir = 1.f / (Dx * Dx + Dy * Dy);
        float ivx = Dx * ir, ivy = -Dy * ir;          // 1/D
        float ax = zx - W.x;                          // z - wr
        float alr = 2.f * (ax * ivx - zy * ivy);
        float ali = 2.f * (ax * ivy + zy * ivx);
        float ber = -2.f * W.y * ivx;
        float bei = -2.f * W.y * ivy;
        unsigned long long ALPHA = pack2(alr, ali);
        unsigned long long BETA  = pack2(ber, bei);
        #pragma unroll
        for (int j = 0; j < 16; ++j) {
            union { float4 f; unsigned long long u64[2]; } c1, c2;
            c1.f = sT1[j][n];
            c2.f = sT2[j][n];
            A0[j] = fma2(c1.u64[0], ALPHA, A0[j]);
            A0[j] = fma2(c1.u64[1], BETA,  A0[j]);
            A1[j] = fma2(c2.u64[0], ALPHA, A1[j]);
            A1[j] = fma2(c2.u64[1], BETA,  A1[j]);
        }
        float4 q = sQ[n];
        A0q = fma2(pack2(q.x, q.x), ALPHA, A0q);
        A0q = fma2(pack2(q.y, q.y), BETA,  A0q);
        A1q = fma2(pack2(q.z, q.z), ALPHA, A1q);
    }

    float2 r0q, r1q;
    unpack2(A0q, r0q.x, r0q.y);
    unpack2(A1q, r1q.x, r1q.y);
    r0q.x *= dt; r0q.y *= dt; r1q.x *= dt; r1q.y *= dt;
    float2 onep = make_float2(1.f + r1q.x, r1q.y);
    float  oin  = 1.f / (onep.x * onep.x + onep.y * onep.y);
    float2 coef = cmulf(r0q, make_float2(onep.x * oin, -onep.y * oin)); // r0q/(1+r1q)

    #pragma unroll
    for (int j = 0; j < 16; ++j) {
        float2 a0j, a1j;
        unpack2(A0[j], a0j.x, a0j.y);
        unpack2(A1[j], a1j.x, a1j.y);
        float2 R0 = make_float2(a0j.x * dt, a0j.y * dt);
        float2 R1 = make_float2(a1j.x * dt, a1j.y * dt);
        float2 corr = cmulf(coef, R1);
        float2 kf = cmulf(csubf(R0, corr), fac);
        g_kf[((c0 + j) * HH + h) * LF + l] = kf;
    }
}

// ---------------- odd bins of the 4096-DFT of the kernel ----------------
// 2-channel complex packing; Hermitian input build fused into the first iFFT's stage-0. (R16-proven)
__global__ __launch_bounds__(256, 3) void k_kernelfft() {
    __shared__ float sre[2 * PADN], sim[2 * PADN];
    int s = threadIdx.x >> 7, u = threadIdx.x & 127;
    int p = blockIdx.x * 2 + s;                       // pair index in [0, 4096)
    int c1 = (p >> 8) * 2;                            // even channel
    int h  = p & 255;
    int ch1 = c1 * HH + h;
    int ch2 = ch1 + HH;                               // channel c1+1, same h
    float* re = sre + s * PADN;
    float* im = sim + s * PADN;

    const float2* kf1 = g_kf + (size_t)ch1 * LF;
    const float2* kf2 = g_kf + (size_t)ch2 * LF;

    {
        float2 x[16];
        #pragma unroll
        for (int m = 0; m < 16; ++m) {
            int a = u + 128 * m;
            bool mir = (a > 1024);
            int idx = mir ? (2048 - a) : a;
            float2 X1 = kf1[idx];
            float2 X2 = kf2[idx];
            x[m] = mir ? make_float2(X1.x + X2.y, X2.x - X1.y)   // conj(X1)+i*conj(X2)
                       : make_float2(X1.x - X2.y, X1.y + X2.x);  // X1 + i*X2
        }
        dft16(x, 1);
        stage0_store(re, im, u, x);
    }
    fft2048_tail<1>(re, im, u);                       // z = (k1 + i*k2) * 2048
    fft2048<0, 1>(re, im, u, 1.0f / 2048.0f);         // Y = FFT(z/2048 * e^{-i*pi*l/2048})

    float2* d1 = g_kodd + (size_t)ch1 * 1024;
    float2* d2 = g_kodd + (size_t)ch2 * 1024;
    for (int j = u; j < 1024; j += 128) {
        int pj = PIX(j), pm = PIX(2047 - j);
        float Pr = re[pj], Pi = im[pj];
        float Mr = re[pm], Mi = im[pm];
        d1[j] = make_float2(0.5f * (Pr + Mr), 0.5f * (Pi - Mi));
        d2[j] = make_float2(0.5f * (Pi + Mi), 0.5f * (Mr - Pr));
    }
}

// ---------------- rfft(pd, 4096) via real packing (2 rows/block) ----------------
__global__ __launch_bounds__(256, 3) void k_pdfft(const float* __restrict__ pd) {
    __shared__ float sre[2 * PADN], sim[2 * PADN];
    int s = threadIdx.x >> 7, u = threadIdx.x & 127;
    int ch = blockIdx.x * 2 + s;                      // b*256 + h
    float* re = sre + s * PADN;
    float* im = sim + s * PADN;

    const float* src = pd + (size_t)ch * LL;
    for (int n = u; n < 2048; n += 128) {
        if (n < 1024) { re[PIX(n)] = src[2 * n]; im[PIX(n)] = src[2 * n + 1]; }
        else          { re[PIX(n)] = 0.f;        im[PIX(n)] = 0.f; }
    }
    fft2048<0, 0>(re, im, u);
    float2* dst = g_pdf + (size_t)ch * 2049;
    for (int k = u; k < 2048; k += 128) {
        float2 Yk = make_float2(re[PIX(k)], im[PIX(k)]);
        int km = (2048 - k) & 2047;
        float2 Ym = make_float2(re[PIX(km)], im[PIX(km)]);
        float2 E = make_float2(0.5f * (Yk.x + Ym.x), 0.5f * (Yk.y - Ym.y));
        float2 D = make_float2(Yk.x - Ym.x, Yk.y + Ym.y);
        float2 O = make_float2(0.5f * D.y, -0.5f * D.x);
        float2 w = g_tw[k];
        dst[k] = caddf(E, cmulf(w, O));
    }
    if (u == 0) {
        float2 Y0 = make_float2(re[PIX(0)], im[PIX(0)]);
        dst[2048] = make_float2(Y0.x - Y0.y, 0.f);
    }
}

// ---------------- conv: spectral build fused into stage-0, dC accumulation fused into stage-2 ----------------
// Only y[n<1024] is used by the packed irfft, and stage-2 registers e[0..3]/f[0..3] are exactly
// that range -> accumulate in registers, never store stage-2 to smem (saves 32 STS+16 LDS+2 syncs/channel).
__global__ __launch_bounds__(256, 3) void k_conv() {
    extern __shared__ char smraw[];
    float*  sre = (float*)smraw;                 // 2*PADN
    float*  sim = sre + 2 * PADN;                // 2*PADN
    float2* sPD = (float2*)(sim + 2 * PADN);     // 2*2049
    int tid = threadIdx.x, s = tid >> 7, u = tid & 127;   // s = batch
    int h = blockIdx.x;
    int split = blockIdx.y;
    float* re = sre + s * PADN;
    float* im = sim + s * PADN;

    for (int b = 0; b < NBATCH; ++b) {
        const float2* pf = g_pdf + ((size_t)b * HH + h) * 2049;
        for (int m = tid; m < 2049; m += 256) sPD[b * 2049 + m] = pf[m];
    }
    float acce[8], accf[8];                      // this thread's 16 owned l-positions (its batch)
    #pragma unroll
    for (int i = 0; i < 8; ++i) { acce[i] = 0.f; accf[i] = 0.f; }
    __syncthreads();

    const float2* sPDs = sPD + s * 2049;
    int i0   = u >> 1;
    int mir0 = (u & 1) ? (1023 - i0) : (1024 - i0);
    int cbeg = split * (CCHN / CSPLIT);
    const float inv2048 = 1.0f / 2048.0f;

    for (int ci = 0; ci < CCHN / CSPLIT; ++ci) {
        int c = cbeg + ci;
        const float2* kf = g_kf   + ((size_t)c * HH + h) * LF;
        const float2* ko = g_kodd + ((size_t)c * HH + h) * 1024;
        const float2* base = (u & 1) ? ko : kf;

        // ---- stage 0 (fused spectral build) ----
        float2 x[16];
        #pragma unroll
        for (int m = 0; m < 16; ++m) {
            int k = u + 128 * m;
            float2 Ka = base[i0 + 64 * m];            // K[k]
            float2 Kb = base[mir0 - 64 * m];          // K[2048-k]
            float2 Xk = cmulf(sPDs[k],        Ka);
            float2 X2 = cmulf(sPDs[2048 - k], Kb);
            float2 E = make_float2(0.5f * (Xk.x + X2.x), 0.5f * (Xk.y - X2.y));
            float2 D = make_float2(Xk.x - X2.x, Xk.y + X2.y);
            float2 w = g_tw[k];
            float2 O = make_float2(0.5f * (D.x * w.x + D.y * w.y),
                                   0.5f * (D.y * w.x - D.x * w.y));   // (D/2)*conj(w)
            x[m] = make_float2(E.x - O.y, E.y + O.x);                 // Y = E + i*O
        }
        dft16(x, 1);
        __syncthreads();                          // protect prior iteration's stage-2 reads
        stage0_store(re, im, u, x);

        // ---- stage 1 ----
        __syncthreads();
        #pragma unroll
        for (int m = 0; m < 16; ++m) { int a = u + 128 * m, i = PIX(a); x[m] = make_float2(re[i], im[i]); }
        {
            int p = u & 15;
            float2 w = g_tw[16 * p];
            w.y = -w.y;                           // inverse
            float2 cur = w;
            #pragma unroll
            for (int m = 1; m < 16; ++m) { x[m] = cmulf(x[m], cur); cur = cmulf(cur, w); }
        }
        dft16(x, 1);
        __syncthreads();
        {
            int basei = ((u >> 4) << 8) + (u & 15);
            #pragma unroll
            for (int m = 0; m < 16; ++m) {
                int d = basei + 16 * m, i = PIX(d);
                float2 v = x[((m & 3) << 2) | (m >> 2)];
                re[i] = v.x; im[i] = v.y;
            }
        }
        __syncthreads();

        // ---- stage 2 (register epilogue: accumulate, no smem store) ----
        float2 e[8], f[8];
        #pragma unroll
        for (int m = 0; m < 8; ++m) {
            int a0 = u + 256 * m, a1 = u + 128 + 256 * m;
            e[m] = make_float2(re[PIX(a0)], im[PIX(a0)]);
            f[m] = make_float2(re[PIX(a1)], im[PIX(a1)]);
        }
        {
            float2 w0 = g_tw[2 * u], w1 = g_tw[2 * (u + 128)];
            w0.y = -w0.y; w1.y = -w1.y;
            float2 c0 = w0, c1 = w1;
            #pragma unroll
            for (int m = 1; m < 8; ++m) {
                e[m] = cmulf(e[m], c0); c0 = cmulf(c0, w0);
                f[m] = cmulf(f[m], c1); c1 = cmulf(c1, w1);
            }
        }
        dft8(e, 1); dft8(f, 1);

        const float* wv = g_dCt + ((size_t)h * CCHN + c) * LL;
        #pragma unroll
        for (int m = 0; m < 4; ++m) {
            int n  = u + 256 * m;                 // e[m] = y[n], n < 1024
            int n2 = n + 128;                     // f[m] = y[n2], n2 < 1024
            float2 w1v = *(const float2*)(wv + 2 * n);
            float2 w2v = *(const float2*)(wv + 2 * n2);
            acce[2 * m]     += e[m].x * inv2048 * w1v.x;
            acce[2 * m + 1] += e[m].y * inv2048 * w1v.y;
            accf[2 * m]     += f[m].x * inv2048 * w2v.x;
            accf[2 * m + 1] += f[m].y * inv2048 * w2v.y;
        }
        __syncthreads();                          // protect stage-2 reads before next stage0_store
    }

    float* p = g_part + (((size_t)split * NBATCH + s) * HH + h) * LL;
    #pragma unroll
    for (int m = 0; m < 4; ++m) {
        int n  = u + 256 * m;
        int n2 = n + 128;
        *(float2*)(p + 2 * n)  = make_float2(acce[2 * m], acce[2 * m + 1]);
        *(float2*)(p + 2 * n2) = make_float2(accf[2 * m], accf[2 * m + 1]);
    }
}

// ---------------- reduce partials -> out ----------------
__global__ void k_reduce(float* __restrict__ out) {
    int i = blockIdx.x * blockDim.x + threadIdx.x;     // over NBATCH*HH*LL
    const int TOT = NBATCH * HH * LL;
    if (i >= TOT) return;
    float v = 0.f;
    #pragma unroll
    for (int sp = 0; sp < CSPLIT; ++sp)
        v += g_part[(size_t)sp * TOT + i];
    out[i] = v;
}

// ---------------- launch ----------------
extern "C" void kernel_launch(void* const* d_in, const int* in_sizes, int n_in,
                              void* d_out, int out_size) {
    const float* log_dt = (const float*)d_in[0];
    const float* B_ri   = (const float*)d_in[1];
    const float* P_ri   = (const float*)d_in[2];
    const float* C_ri   = (const float*)d_in[3];
    const float* iwr    = (const float*)d_in[4];
    const float* wim    = (const float*)d_in[5];
    const float* dC     = (const float*)d_in[6];
    const float* pd     = (const float*)d_in[7];
    float* out = (float*)d_out;
    (void)in_sizes; (void)n_in; (void)out_size;

    const int SM_CONV = (2 * PADN * 2) * (int)sizeof(float)       // sre+sim
                      + 2 * 2049 * (int)sizeof(float2);           // sPD both batches
    cudaFuncSetAttribute(k_conv, cudaFuncAttributeMaxDynamicSharedMemorySize, SM_CONV);

    k_init_tw<<<8, 256>>>();
    k_transpose<<<dim3(LL / 32, HH), 256>>>(dC);
    k_cauchy<<<dim3((LF + 127) / 128, HH, 2), 128>>>(log_dt, B_ri, P_ri, C_ri, iwr, wim);
    k_kernelfft<<<CCHN * HH / 4, 256>>>();
    k_pdfft<<<NBATCH * HH / 2, 256>>>(pd);
    k_conv<<<dim3(HH, CSPLIT), 256, SM_CONV>>>();
    k_reduce<<<(NBATCH * HH * LL + 255) / 256, 256>>>(out);
}